// round 10
// baseline (speedup 1.0000x reference)
#include <cuda_runtime.h>
#include <math.h>
#include <cstdint>

#define BATCH_ 16
#define SEQ_ 512
#define DIM_ 2048
#define NH_ 16
#define HD_ 128
#define ROWS_ (BATCH_*SEQ_)    // 8192
#define QKVN_ (3*DIM_)         // 6144

// ---- scratch (static device globals; no runtime allocation) ----
__device__ float g_qkv[(size_t)ROWS_ * QKVN_];
__device__ float g_q[(size_t)BATCH_*NH_*SEQ_*HD_];
__device__ float g_k[(size_t)BATCH_*NH_*SEQ_*HD_];
__device__ float g_v[(size_t)BATCH_*NH_*SEQ_*HD_];
__device__ float g_y[(size_t)ROWS_ * DIM_];
__device__ float g_xr[(size_t)ROWS_ * DIM_];       // tf32-rounded x
__device__ float g_wqkvr[(size_t)DIM_ * QKVN_];    // tf32-rounded Wqkv
__device__ float g_woutr[(size_t)DIM_ * DIM_];     // tf32-rounded Wout

extern __shared__ char dyn_smem[];

// ============================================================
// helpers
// ============================================================
__device__ __forceinline__ uint32_t f2tf32(float f) {
    uint32_t r;
    asm("cvt.rna.tf32.f32 %0, %1;" : "=r"(r) : "f"(f));
    return r;
}
__device__ __forceinline__ float tf32r(float f) { return __uint_as_float(f2tf32(f)); }

__device__ __forceinline__ void mma_tf32(float* c, const uint32_t* a, const uint32_t* b) {
    asm volatile(
        "mma.sync.aligned.m16n8k8.row.col.f32.tf32.tf32.f32 "
        "{%0,%1,%2,%3}, {%4,%5,%6,%7}, {%8,%9}, {%0,%1,%2,%3};"
        : "+f"(c[0]), "+f"(c[1]), "+f"(c[2]), "+f"(c[3])
        : "r"(a[0]), "r"(a[1]), "r"(a[2]), "r"(a[3]), "r"(b[0]), "r"(b[1]));
}

__device__ __forceinline__ uint32_t smem_u32(const void* p) {
    uint32_t a;
    asm("{ .reg .u64 t; cvta.to.shared.u64 t, %1; cvt.u32.u64 %0, t; }" : "=r"(a) : "l"(p));
    return a;
}
__device__ __forceinline__ void cp16(uint32_t dst, const void* src) {
    asm volatile("cp.async.cg.shared.global [%0], [%1], 16;" :: "r"(dst), "l"(src) : "memory");
}
#define CP_COMMIT() asm volatile("cp.async.commit_group;" ::: "memory")
#define CP_WAIT(n)  asm volatile("cp.async.wait_group %0;" :: "n"(n) : "memory")

// ============================================================
// merged tf32 rounding: one launch for x, Wqkv, Wout
// ============================================================
#define N4_X   (ROWS_*DIM_/4)     // 4194304
#define N4_WQ  (DIM_*QKVN_/4)     // 3145728
#define N4_WO  (DIM_*DIM_/4)      // 1048576
#define N4_ALL (N4_X + N4_WQ + N4_WO)

__global__ __launch_bounds__(256) void round_all_kernel(
    const float4* __restrict__ x, const float4* __restrict__ wq, const float4* __restrict__ wo,
    float4* __restrict__ xr, float4* __restrict__ wqr, float4* __restrict__ wor)
{
    int i = blockIdx.x * blockDim.x + threadIdx.x;
    const float4* in;
    float4* out;
    int idx;
    if (i < N4_X)            { in = x;  out = xr;  idx = i; }
    else if (i < N4_X+N4_WQ) { in = wq; out = wqr; idx = i - N4_X; }
    else if (i < N4_ALL)     { in = wo; out = wor; idx = i - N4_X - N4_WQ; }
    else return;
    float4 v = in[idx];
    v.x = tf32r(v.x); v.y = tf32r(v.y); v.z = tf32r(v.z); v.w = tf32r(v.w);
    out[idx] = v;
}

// ============================================================
// TF32 GEMM v2: 128x256 block tile, 64x64 warp tiles (8 warps),
// BK=32, 3-stage cp.async. C[M,N] = A[M,K] @ B[K,N].
// grid (N/256, M/128), 256 threads. LDS/MMA ratio 1.0.
// ============================================================
#define GA_STRIDE 36
#define GB_STRIDE 264
#define GA_U32 (128 * GA_STRIDE)      // 4608
#define GB_U32 (32 * GB_STRIDE)       // 8448
#define GSTAGE_U32 (GA_U32 + GB_U32)  // 13056
#define GEMM_SMEM_BYTES (3 * GSTAGE_U32 * 4)   // 156672

__global__ __launch_bounds__(256) void tf32_gemm_async(
    const float* __restrict__ A, const float* __restrict__ B,
    float* __restrict__ C, int M, int N, int K)
{
    const uint32_t sbase = smem_u32(dyn_smem);
    uint32_t* smu = (uint32_t*)dyn_smem;

    const int tid = threadIdx.x;
    const int lane = tid & 31;
    const int w = tid >> 5;
    const int wm = (w & 1) * 64;           // warp row offset (2 warp-rows)
    const int wn = (w >> 1) * 64;          // warp col offset (4 warp-cols)
    const int grp = lane >> 2;
    const int qid = lane & 3;

    const int bm = blockIdx.y, bn = blockIdx.x;
    const float* Ab = A + (size_t)bm * 128 * K;
    const float* Bb = B + (size_t)bn * 256;

    const int nch = K / 32;

    auto issue = [&](int ch, int s) {
        const uint32_t sa = sbase + (uint32_t)(s * GSTAGE_U32) * 4;
        const uint32_t sb = sa + GA_U32 * 4;
#pragma unroll
        for (int i = 0; i < 4; i++) {
            int cidx = tid + i * 256;          // 0..1023: A 128 rows x 8 chunks
            int r = cidx >> 3, c4 = cidx & 7;
            cp16(sa + (uint32_t)(r * GA_STRIDE + c4 * 4) * 4,
                 Ab + (size_t)r * K + ch * 32 + c4 * 4);
        }
#pragma unroll
        for (int i = 0; i < 8; i++) {
            int cidx = tid + i * 256;           // 0..2047: B 32 rows x 64 chunks
            int r = cidx >> 6, c4 = cidx & 63;
            cp16(sb + (uint32_t)(r * GB_STRIDE + c4 * 4) * 4,
                 Bb + (size_t)(ch * 32 + r) * N + c4 * 4);
        }
        CP_COMMIT();
    };

    float c[4][8][4];
#pragma unroll
    for (int i = 0; i < 4; i++)
#pragma unroll
        for (int j = 0; j < 8; j++)
#pragma unroll
            for (int q = 0; q < 4; q++) c[i][j][q] = 0.f;

    issue(0, 0);
    issue(1, 1);

    for (int ch = 0; ch < nch; ch++) {
        if (ch + 1 < nch) { CP_WAIT(1); } else { CP_WAIT(0); }
        __syncthreads();

        const uint32_t* As = smu + (ch % 3) * GSTAGE_U32;
        const uint32_t* Bs = As + GA_U32;
#pragma unroll
        for (int ks = 0; ks < 4; ks++) {
            const int kk = ks * 8;
            uint32_t af[4][4], bf[8][2];
#pragma unroll
            for (int i = 0; i < 4; i++) {
                const int m = wm + i * 16 + grp;
                af[i][0] = As[m * GA_STRIDE + kk + qid];
                af[i][1] = As[(m + 8) * GA_STRIDE + kk + qid];
                af[i][2] = As[m * GA_STRIDE + kk + qid + 4];
                af[i][3] = As[(m + 8) * GA_STRIDE + kk + qid + 4];
            }
#pragma unroll
            for (int j = 0; j < 8; j++) {
                const int n = wn + j * 8 + grp;
                bf[j][0] = Bs[(kk + qid) * GB_STRIDE + n];
                bf[j][1] = Bs[(kk + qid + 4) * GB_STRIDE + n];
            }
#pragma unroll
            for (int i = 0; i < 4; i++)
#pragma unroll
                for (int j = 0; j < 8; j++)
                    mma_tf32(c[i][j], af[i], bf[j]);
        }

        if (ch + 2 < nch) issue(ch + 2, (ch + 2) % 3);
    }

#pragma unroll
    for (int i = 0; i < 4; i++) {
        const int row = bm * 128 + wm + i * 16 + grp;
#pragma unroll
        for (int j = 0; j < 8; j++) {
            const int col = bn * 256 + wn + j * 8 + qid * 2;
            *(float2*)(C + (size_t)row * N + col)       = make_float2(c[i][j][0], c[i][j][1]);
            *(float2*)(C + (size_t)(row + 8) * N + col) = make_float2(c[i][j][2], c[i][j][3]);
        }
    }
}

// ============================================================
// RoPE + split -> Q,K,V in [B,H,T,hd], tf32-rounded, Q pre-scaled.
// ============================================================
__global__ __launch_bounds__(256) void rope_split_kernel(
    const float* __restrict__ qkv,
    float* __restrict__ Q, float* __restrict__ Kd, float* __restrict__ V)
{
    int gid = blockIdx.x * blockDim.x + threadIdx.x;
    int d = gid & 127;
    int t = (gid >> 7) & 511;
    int h = (gid >> 16) & 15;
    int b = gid >> 20;

    size_t base = ((size_t)(b * SEQ_ + t)) * QKVN_ + h * HD_;
    size_t oidx = ((size_t)((b * NH_ + h) * SEQ_ + t)) * HD_ + d;

    V[oidx] = tf32r(qkv[base + 2 * DIM_ + d]);

    float qv, kv;
    if (d < 16) {
        int i = (d < 8) ? d : d - 8;
        float inv = expf(-(float)i * (9.210340371976184f / 8.0f));
        float fr = (float)t * inv;
        float s, c;
        sincosf(fr, &s, &c);
        float q1 = qkv[base + i],         q2 = qkv[base + i + 8];
        float k1 = qkv[base + DIM_ + i],  k2 = qkv[base + DIM_ + i + 8];
        if (d < 8) { qv = q1 * c - q2 * s; kv = k1 * c - k2 * s; }
        else       { qv = q2 * c + q1 * s; kv = k2 * c + k1 * s; }
    } else {
        qv = qkv[base + d];
        kv = qkv[base + DIM_ + d];
    }
    Q[oidx] = tf32r(qv * 0.08838834764831845f);
    Kd[oidx] = tf32r(kv);
}

// ============================================================
// Tensor-core flash attention v3 (unchanged from round 8).
// ============================================================
#define AK_STRIDE 132
#define AV_STRIDE 136
#define AP_STRIDE 76
#define AK_U32 (64 * AK_STRIDE)
#define AV_U32 (64 * AV_STRIDE)
#define AV_OFF (2 * AK_U32)
#define AP_OFF (AV_OFF + 2 * AV_U32)
#define ATT_SMEM_BYTES ((AP_OFF + 8 * 16 * AP_STRIDE) * 4)

__global__ __launch_bounds__(256, 1) void attn_mma_kernel(
    const float* __restrict__ Q, const float* __restrict__ K,
    const float* __restrict__ V, float* __restrict__ Y)
{
    const uint32_t sbase = smem_u32(dyn_smem);
    uint32_t* smu = (uint32_t*)dyn_smem;

    const int qt = blockIdx.x, bh = blockIdx.y;
    const int tid = threadIdx.x;
    const int lane = tid & 31;
    const int w = tid >> 5;
    const int grp = lane >> 2;
    const int qid = lane & 3;

    const float* Qh = Q + (size_t)bh * SEQ_ * HD_ + (size_t)qt * 128 * HD_;
    const float* Kh = K + (size_t)bh * SEQ_ * HD_;
    const float* Vh = V + (size_t)bh * SEQ_ * HD_;

    const int nch = 2 * qt + 2;

    uint32_t qf[16][4];
    {
#pragma unroll
        for (int i = 0; i < 16; i++) {
            int idx = tid + i * 256;
            int r = idx >> 5, c4 = idx & 31;
            cp16(sbase + (uint32_t)(r * AK_STRIDE + c4 * 4) * 4,
                 Qh + (size_t)r * HD_ + c4 * 4);
        }
        CP_COMMIT();
        CP_WAIT(0);
        __syncthreads();
        const int qrow = w * 16 + grp;
#pragma unroll
        for (int kk = 0; kk < 16; kk++) {
            const uint32_t* qb = smu + qrow * AK_STRIDE + kk * 8;
            qf[kk][0] = qb[qid];
            qf[kk][1] = qb[8 * AK_STRIDE + qid];
            qf[kk][2] = qb[qid + 4];
            qf[kk][3] = qb[8 * AK_STRIDE + qid + 4];
        }
        __syncthreads();
    }

    auto issue_kv = [&](int kc, int s) {
        const uint32_t ks = sbase + (uint32_t)(s * AK_U32) * 4;
        const uint32_t vs = sbase + (uint32_t)(AV_OFF + s * AV_U32) * 4;
#pragma unroll
        for (int i = 0; i < 8; i++) {
            int cidx = tid + i * 256;
            int r = cidx >> 5, c4 = cidx & 31;
            cp16(ks + (uint32_t)(r * AK_STRIDE + c4 * 4) * 4,
                 Kh + (size_t)(kc * 64 + r) * HD_ + c4 * 4);
            cp16(vs + (uint32_t)(r * AV_STRIDE + c4 * 4) * 4,
                 Vh + (size_t)(kc * 64 + r) * HD_ + c4 * 4);
        }
        CP_COMMIT();
    };

    issue_kv(0, 0);
    issue_kv(1, 1);

    uint32_t* Pw = smu + AP_OFF + w * 16 * AP_STRIDE;

    float o[16][4];
#pragma unroll
    for (int j = 0; j < 16; j++)
#pragma unroll
        for (int q = 0; q < 4; q++) o[j][q] = 0.f;
    float m0 = -1e30f, m1 = -1e30f, l0 = 0.f, l1 = 0.f;

    const int r0g = qt * 128 + w * 16 + grp;
    const int r1g = r0g + 8;

    for (int kc = 0; kc < nch; kc++) {
        if (kc + 1 < nch) { CP_WAIT(1); } else { CP_WAIT(0); }
        __syncthreads();

        const uint32_t* Ksb = smu + (kc & 1) * AK_U32;
        const uint32_t* Vsb = smu + AV_OFF + (kc & 1) * AV_U32;

        float s[8][4];
#pragma unroll
        for (int j = 0; j < 8; j++)
#pragma unroll
            for (int q = 0; q < 4; q++) s[j][q] = 0.f;

#pragma unroll
        for (int kk = 0; kk < 16; kk++) {
#pragma unroll
            for (int j = 0; j < 8; j++) {
                uint32_t b[2];
                const uint32_t* kb = Ksb + (j * 8 + grp) * AK_STRIDE + kk * 8;
                b[0] = kb[qid];
                b[1] = kb[qid + 4];
                mma_tf32(s[j], qf[kk], b);
            }
        }

        const int cbase = kc * 64;
#pragma unroll
        for (int j = 0; j < 8; j++) {
            const int c0 = cbase + j * 8 + 2 * qid;
            if (c0 > r0g)     s[j][0] = -1e30f;
            if (c0 + 1 > r0g) s[j][1] = -1e30f;
            if (c0 > r1g)     s[j][2] = -1e30f;
            if (c0 + 1 > r1g) s[j][3] = -1e30f;
        }

        float mc0 = -1e30f, mc1 = -1e30f;
#pragma unroll
        for (int j = 0; j < 8; j++) {
            mc0 = fmaxf(mc0, fmaxf(s[j][0], s[j][1]));
            mc1 = fmaxf(mc1, fmaxf(s[j][2], s[j][3]));
        }
        mc0 = fmaxf(mc0, __shfl_xor_sync(0xFFFFFFFF, mc0, 1));
        mc0 = fmaxf(mc0, __shfl_xor_sync(0xFFFFFFFF, mc0, 2));
        mc1 = fmaxf(mc1, __shfl_xor_sync(0xFFFFFFFF, mc1, 1));
        mc1 = fmaxf(mc1, __shfl_xor_sync(0xFFFFFFFF, mc1, 2));

        const float mn0 = fmaxf(m0, mc0);
        const float mn1 = fmaxf(m1, mc1);
        const float corr0 = __expf(m0 - mn0);
        const float corr1 = __expf(m1 - mn1);
        m0 = mn0; m1 = mn1;

        float ls0 = 0.f, ls1 = 0.f;
#pragma unroll
        for (int j = 0; j < 8; j++) {
            s[j][0] = __expf(s[j][0] - mn0);
            s[j][1] = __expf(s[j][1] - mn0);
            s[j][2] = __expf(s[j][2] - mn1);
            s[j][3] = __expf(s[j][3] - mn1);
            ls0 += s[j][0] + s[j][1];
            ls1 += s[j][2] + s[j][3];
        }
        ls0 += __shfl_xor_sync(0xFFFFFFFF, ls0, 1);
        ls0 += __shfl_xor_sync(0xFFFFFFFF, ls0, 2);
        ls1 += __shfl_xor_sync(0xFFFFFFFF, ls1, 1);
        ls1 += __shfl_xor_sync(0xFFFFFFFF, ls1, 2);
        l0 = l0 * corr0 + ls0;
        l1 = l1 * corr1 + ls1;

#pragma unroll
        for (int j = 0; j < 16; j++) {
            o[j][0] *= corr0; o[j][1] *= corr0;
            o[j][2] *= corr1; o[j][3] *= corr1;
        }

#pragma unroll
        for (int j = 0; j < 8; j++) {
            uint32_t* p0 = Pw + grp * AP_STRIDE + j * 8 + 2 * qid;
            p0[0] = f2tf32(s[j][0]);
            p0[1] = f2tf32(s[j][1]);
            uint32_t* p1 = p0 + 8 * AP_STRIDE;
            p1[0] = f2tf32(s[j][2]);
            p1[1] = f2tf32(s[j][3]);
        }
        __syncwarp();

#pragma unroll
        for (int kk = 0; kk < 8; kk++) {
            uint32_t a[4];
            const uint32_t* pb = Pw + grp * AP_STRIDE + kk * 8;
            a[0] = pb[qid];
            a[1] = pb[8 * AP_STRIDE + qid];
            a[2] = pb[qid + 4];
            a[3] = pb[8 * AP_STRIDE + qid + 4];
#pragma unroll
            for (int j = 0; j < 16; j++) {
                uint32_t b[2];
                const uint32_t* vb = Vsb + (kk * 8 + qid) * AV_STRIDE + j * 8 + grp;
                b[0] = vb[0];
                b[1] = vb[4 * AV_STRIDE];
                mma_tf32(o[j], a, b);
            }
        }

        __syncthreads();
        if (kc + 2 < nch) issue_kv(kc + 2, kc & 1);
    }

    const float inv0 = 1.f / l0;
    const float inv1 = 1.f / l1;
    const int b = bh >> 4, h = bh & 15;
    float* y0 = Y + ((size_t)(b * SEQ_ + r0g)) * DIM_ + h * HD_;
    float* y1 = Y + ((size_t)(b * SEQ_ + r1g)) * DIM_ + h * HD_;
#pragma unroll
    for (int j = 0; j < 16; j++) {
        const int col = j * 8 + 2 * qid;
        *(float2*)(y0 + col) = make_float2(tf32r(o[j][0] * inv0), tf32r(o[j][1] * inv0));
        *(float2*)(y1 + col) = make_float2(tf32r(o[j][2] * inv1), tf32r(o[j][3] * inv1));
    }
}

// ============================================================
// launch
// ============================================================
extern "C" void kernel_launch(void* const* d_in, const int* in_sizes, int n_in,
                              void* d_out, int out_size)
{
    const float* x    = (const float*)d_in[0];
    const float* Wqkv = (const float*)d_in[1];
    const float* Wout = (const float*)d_in[2];
    float* out = (float*)d_out;

    float *qkv, *Q, *K, *V, *Y, *xr, *wqkvr, *woutr;
    cudaGetSymbolAddress((void**)&qkv, g_qkv);
    cudaGetSymbolAddress((void**)&Q, g_q);
    cudaGetSymbolAddress((void**)&K, g_k);
    cudaGetSymbolAddress((void**)&V, g_v);
    cudaGetSymbolAddress((void**)&Y, g_y);
    cudaGetSymbolAddress((void**)&xr, g_xr);
    cudaGetSymbolAddress((void**)&wqkvr, g_wqkvr);
    cudaGetSymbolAddress((void**)&woutr, g_woutr);

    cudaFuncSetAttribute(tf32_gemm_async, cudaFuncAttributeMaxDynamicSharedMemorySize, GEMM_SMEM_BYTES);
    cudaFuncSetAttribute(attn_mma_kernel, cudaFuncAttributeMaxDynamicSharedMemorySize, ATT_SMEM_BYTES);

    // 0) pre-round operands to tf32 (single launch)
    round_all_kernel<<<(N4_ALL + 255) / 256, 256>>>(
        (const float4*)x, (const float4*)Wqkv, (const float4*)Wout,
        (float4*)xr, (float4*)wqkvr, (float4*)woutr);

    // 1) qkv = x @ Wqkv   (128x256 tiles)
    tf32_gemm_async<<<dim3(QKVN_ / 256, ROWS_ / 128), 256, GEMM_SMEM_BYTES>>>(xr, wqkvr, qkv, ROWS_, QKVN_, DIM_);

    // 2) split + rope (+ scale folded into Q), outputs tf32-rounded
    rope_split_kernel<<<(BATCH_ * NH_ * SEQ_ * HD_) / 256, 256>>>(qkv, Q, K, V);

    // 3) causal attention -> Y (tf32-rounded)
    attn_mma_kernel<<<dim3(SEQ_ / 128, BATCH_ * NH_), 256, ATT_SMEM_BYTES>>>(Q, K, V, Y);

    // 4) out = Y @ Wout
    tf32_gemm_async<<<dim3(DIM_ / 256, ROWS_ / 128), 256, GEMM_SMEM_BYTES>>>(Y, woutr, out, ROWS_, DIM_, DIM_);
}

// round 11
// speedup vs baseline: 1.0968x; 1.0968x over previous
#include <cuda_runtime.h>
#include <math.h>
#include <cstdint>

#define BATCH_ 16
#define SEQ_ 512
#define DIM_ 2048
#define NH_ 16
#define HD_ 128
#define ROWS_ (BATCH_*SEQ_)    // 8192
#define QKVN_ (3*DIM_)         // 6144

// ---- scratch (static device globals; no runtime allocation) ----
__device__ float g_qkv[(size_t)ROWS_ * QKVN_];
__device__ float g_q[(size_t)BATCH_*NH_*SEQ_*HD_];
__device__ float g_k[(size_t)BATCH_*NH_*SEQ_*HD_];
__device__ float g_v[(size_t)BATCH_*NH_*SEQ_*HD_];
__device__ float g_y[(size_t)ROWS_ * DIM_];
__device__ float g_xr[(size_t)ROWS_ * DIM_];       // tf32-rounded x
__device__ float g_wqkvt[(size_t)DIM_ * QKVN_];    // Wqkv^T [6144][2048], tf32
__device__ float g_woutt[(size_t)DIM_ * DIM_];     // Wout^T [2048][2048], tf32

extern __shared__ char dyn_smem[];

// ============================================================
// helpers
// ============================================================
__device__ __forceinline__ uint32_t f2tf32(float f) {
    uint32_t r;
    asm("cvt.rna.tf32.f32 %0, %1;" : "=r"(r) : "f"(f));
    return r;
}
__device__ __forceinline__ float tf32r(float f) { return __uint_as_float(f2tf32(f)); }

__device__ __forceinline__ void mma_tf32(float* c, const uint32_t* a, const uint32_t* b) {
    asm volatile(
        "mma.sync.aligned.m16n8k8.row.col.f32.tf32.tf32.f32 "
        "{%0,%1,%2,%3}, {%4,%5,%6,%7}, {%8,%9}, {%0,%1,%2,%3};"
        : "+f"(c[0]), "+f"(c[1]), "+f"(c[2]), "+f"(c[3])
        : "r"(a[0]), "r"(a[1]), "r"(a[2]), "r"(a[3]), "r"(b[0]), "r"(b[1]));
}

__device__ __forceinline__ void ldsm_x4(uint32_t* r, uint32_t addr) {
    asm volatile("ldmatrix.sync.aligned.m8n8.x4.shared.b16 {%0,%1,%2,%3}, [%4];"
        : "=r"(r[0]), "=r"(r[1]), "=r"(r[2]), "=r"(r[3]) : "r"(addr));
}

__device__ __forceinline__ uint32_t smem_u32(const void* p) {
    uint32_t a;
    asm("{ .reg .u64 t; cvta.to.shared.u64 t, %1; cvt.u32.u64 %0, t; }" : "=r"(a) : "l"(p));
    return a;
}
__device__ __forceinline__ void cp16(uint32_t dst, const void* src) {
    asm volatile("cp.async.cg.shared.global [%0], [%1], 16;" :: "r"(dst), "l"(src) : "memory");
}
#define CP_COMMIT() asm volatile("cp.async.commit_group;" ::: "memory")
#define CP_WAIT(n)  asm volatile("cp.async.wait_group %0;" :: "n"(n) : "memory")

// ============================================================
// x rounding (elementwise) + fused round+transpose for weights
// ============================================================
#define N4_X (ROWS_*DIM_/4)

__global__ __launch_bounds__(256) void round_x_kernel(
    const float4* __restrict__ in, float4* __restrict__ out, int n4)
{
    int i = blockIdx.x * blockDim.x + threadIdx.x;
    if (i < n4) {
        float4 v = in[i];
        v.x = tf32r(v.x); v.y = tf32r(v.y); v.z = tf32r(v.z); v.w = tf32r(v.w);
        out[i] = v;
    }
}

// out[c][r] = tf32r(in[r][c]);  in: [R][C].  grid (C/32, R/32), block (32,8)
__global__ __launch_bounds__(256) void transpose_round_kernel(
    const float* __restrict__ in, float* __restrict__ out, int R, int C)
{
    __shared__ float t[32][33];
    const int bx = blockIdx.x * 32, by = blockIdx.y * 32;
    const int tx = threadIdx.x, ty = threadIdx.y;
#pragma unroll
    for (int i = 0; i < 4; i++)
        t[ty + i * 8][tx] = tf32r(in[(size_t)(by + ty + i * 8) * C + bx + tx]);
    __syncthreads();
#pragma unroll
    for (int i = 0; i < 4; i++)
        out[(size_t)(bx + ty + i * 8) * R + by + tx] = t[tx][ty + i * 8];
}

// ============================================================
// TF32 GEMM v3 (ldmatrix): C[M,N] = A[M,K] @ Bt[N,K]^T.
// Both operands K-major [rows][K], tf32 pre-rounded.
// 128x128 block tile, 64x32 warp tiles, BK=32, 3-stage cp.async.
// Fragments via LDSM.x4; smem stride 36 floats (conflict-free).
// ============================================================
#define GK_STRIDE 36
#define GT_U32 (128 * GK_STRIDE)          // 4608 per tile
#define GSTAGE_U32 (2 * GT_U32)           // 9216
#define GEMM_SMEM_BYTES (3 * GSTAGE_U32 * 4)   // 110592 -> 2 CTAs/SM

__global__ __launch_bounds__(256) void tf32_gemm_ldsm(
    const float* __restrict__ A, const float* __restrict__ Bt,
    float* __restrict__ C, int M, int N, int K)
{
    const uint32_t sbase = smem_u32(dyn_smem);

    const int tid = threadIdx.x;
    const int lane = tid & 31;
    const int w = tid >> 5;
    const int wm = (w & 1) * 64;
    const int wn = (w >> 1) * 32;
    const int grp = lane >> 2;
    const int qid = lane & 3;

    // ldmatrix lane geometry (A and B tile feeds)
    const int a_r = (lane & 7) + ((lane >> 3) & 1) * 8;  // 0..15
    const int a_c = (lane >> 4) * 4;                     // 0 or 4
    const int b_r = (lane & 7) + (lane >> 4) * 8;        // 0..15
    const int b_c = ((lane >> 3) & 1) * 4;               // 0 or 4

    const int bm = blockIdx.y, bn = blockIdx.x;
    const float* Ab = A + (size_t)bm * 128 * K;
    const float* Bb = Bt + (size_t)bn * 128 * K;

    const int nch = K / 32;

    auto issue = [&](int ch, int s) {
        const uint32_t sa = sbase + (uint32_t)(s * GSTAGE_U32) * 4;
        const uint32_t sb = sa + GT_U32 * 4;
#pragma unroll
        for (int i = 0; i < 4; i++) {
            int cidx = tid + i * 256;          // 128 rows x 8 chunks
            int r = cidx >> 3, c4 = cidx & 7;
            uint32_t off = (uint32_t)(r * GK_STRIDE + c4 * 4) * 4;
            const float* ga = Ab + (size_t)r * K + ch * 32 + c4 * 4;
            const float* gb = Bb + (size_t)r * K + ch * 32 + c4 * 4;
            cp16(sa + off, ga);
            cp16(sb + off, gb);
        }
        CP_COMMIT();
    };

    float c[4][4][4];
#pragma unroll
    for (int i = 0; i < 4; i++)
#pragma unroll
        for (int j = 0; j < 4; j++)
#pragma unroll
            for (int q = 0; q < 4; q++) c[i][j][q] = 0.f;

    issue(0, 0);
    issue(1, 1);

    for (int ch = 0; ch < nch; ch++) {
        if (ch + 1 < nch) { CP_WAIT(1); } else { CP_WAIT(0); }
        __syncthreads();

        const uint32_t abase = sbase + (uint32_t)((ch % 3) * GSTAGE_U32) * 4;
        const uint32_t bbase = abase + GT_U32 * 4;
#pragma unroll
        for (int ks = 0; ks < 4; ks++) {
            const int kk = ks * 8;
            uint32_t af[4][4], bf[4][2];
#pragma unroll
            for (int i = 0; i < 4; i++)
                ldsm_x4(af[i], abase + (uint32_t)((wm + i * 16 + a_r) * GK_STRIDE + kk + a_c) * 4);
#pragma unroll
            for (int j2 = 0; j2 < 2; j2++) {
                uint32_t r4[4];
                ldsm_x4(r4, bbase + (uint32_t)((wn + j2 * 16 + b_r) * GK_STRIDE + kk + b_c) * 4);
                bf[2 * j2][0] = r4[0]; bf[2 * j2][1] = r4[1];
                bf[2 * j2 + 1][0] = r4[2]; bf[2 * j2 + 1][1] = r4[3];
            }
#pragma unroll
            for (int i = 0; i < 4; i++)
#pragma unroll
                for (int j = 0; j < 4; j++)
                    mma_tf32(c[i][j], af[i], bf[j]);
        }

        if (ch + 2 < nch) issue(ch + 2, (ch + 2) % 3);
    }

#pragma unroll
    for (int i = 0; i < 4; i++) {
        const int row = bm * 128 + wm + i * 16 + grp;
#pragma unroll
        for (int j = 0; j < 4; j++) {
            const int col = bn * 128 + wn + j * 8 + qid * 2;
            *(float2*)(C + (size_t)row * N + col)       = make_float2(c[i][j][0], c[i][j][1]);
            *(float2*)(C + (size_t)(row + 8) * N + col) = make_float2(c[i][j][2], c[i][j][3]);
        }
    }
}

// ============================================================
// RoPE + split -> Q,K,V in [B,H,T,hd], tf32-rounded, Q pre-scaled.
// ============================================================
__global__ __launch_bounds__(256) void rope_split_kernel(
    const float* __restrict__ qkv,
    float* __restrict__ Q, float* __restrict__ Kd, float* __restrict__ V)
{
    int gid = blockIdx.x * blockDim.x + threadIdx.x;
    int d = gid & 127;
    int t = (gid >> 7) & 511;
    int h = (gid >> 16) & 15;
    int b = gid >> 20;

    size_t base = ((size_t)(b * SEQ_ + t)) * QKVN_ + h * HD_;
    size_t oidx = ((size_t)((b * NH_ + h) * SEQ_ + t)) * HD_ + d;

    V[oidx] = tf32r(qkv[base + 2 * DIM_ + d]);

    float qv, kv;
    if (d < 16) {
        int i = (d < 8) ? d : d - 8;
        float inv = expf(-(float)i * (9.210340371976184f / 8.0f));
        float fr = (float)t * inv;
        float s, c;
        sincosf(fr, &s, &c);
        float q1 = qkv[base + i],         q2 = qkv[base + i + 8];
        float k1 = qkv[base + DIM_ + i],  k2 = qkv[base + DIM_ + i + 8];
        if (d < 8) { qv = q1 * c - q2 * s; kv = k1 * c - k2 * s; }
        else       { qv = q2 * c + q1 * s; kv = k2 * c + k1 * s; }
    } else {
        qv = qkv[base + d];
        kv = qkv[base + DIM_ + d];
    }
    Q[oidx] = tf32r(qv * 0.08838834764831845f);
    Kd[oidx] = tf32r(kv);
}

// ============================================================
// Tensor-core flash attention v3 (unchanged; measured 179 us).
// ============================================================
#define AK_STRIDE 132
#define AV_STRIDE 136
#define AP_STRIDE 76
#define AK_U32 (64 * AK_STRIDE)
#define AV_U32 (64 * AV_STRIDE)
#define AV_OFF (2 * AK_U32)
#define AP_OFF (AV_OFF + 2 * AV_U32)
#define ATT_SMEM_BYTES ((AP_OFF + 8 * 16 * AP_STRIDE) * 4)

__global__ __launch_bounds__(256, 1) void attn_mma_kernel(
    const float* __restrict__ Q, const float* __restrict__ K,
    const float* __restrict__ V, float* __restrict__ Y)
{
    const uint32_t sbase = smem_u32(dyn_smem);
    uint32_t* smu = (uint32_t*)dyn_smem;

    const int qt = blockIdx.x, bh = blockIdx.y;
    const int tid = threadIdx.x;
    const int lane = tid & 31;
    const int w = tid >> 5;
    const int grp = lane >> 2;
    const int qid = lane & 3;

    const float* Qh = Q + (size_t)bh * SEQ_ * HD_ + (size_t)qt * 128 * HD_;
    const float* Kh = K + (size_t)bh * SEQ_ * HD_;
    const float* Vh = V + (size_t)bh * SEQ_ * HD_;

    const int nch = 2 * qt + 2;

    uint32_t qf[16][4];
    {
#pragma unroll
        for (int i = 0; i < 16; i++) {
            int idx = tid + i * 256;
            int r = idx >> 5, c4 = idx & 31;
            cp16(sbase + (uint32_t)(r * AK_STRIDE + c4 * 4) * 4,
                 Qh + (size_t)r * HD_ + c4 * 4);
        }
        CP_COMMIT();
        CP_WAIT(0);
        __syncthreads();
        const int qrow = w * 16 + grp;
#pragma unroll
        for (int kk = 0; kk < 16; kk++) {
            const uint32_t* qb = smu + qrow * AK_STRIDE + kk * 8;
            qf[kk][0] = qb[qid];
            qf[kk][1] = qb[8 * AK_STRIDE + qid];
            qf[kk][2] = qb[qid + 4];
            qf[kk][3] = qb[8 * AK_STRIDE + qid + 4];
        }
        __syncthreads();
    }

    auto issue_kv = [&](int kc, int s) {
        const uint32_t ks = sbase + (uint32_t)(s * AK_U32) * 4;
        const uint32_t vs = sbase + (uint32_t)(AV_OFF + s * AV_U32) * 4;
#pragma unroll
        for (int i = 0; i < 8; i++) {
            int cidx = tid + i * 256;
            int r = cidx >> 5, c4 = cidx & 31;
            cp16(ks + (uint32_t)(r * AK_STRIDE + c4 * 4) * 4,
                 Kh + (size_t)(kc * 64 + r) * HD_ + c4 * 4);
            cp16(vs + (uint32_t)(r * AV_STRIDE + c4 * 4) * 4,
                 Vh + (size_t)(kc * 64 + r) * HD_ + c4 * 4);
        }
        CP_COMMIT();
    };

    issue_kv(0, 0);
    issue_kv(1, 1);

    uint32_t* Pw = smu + AP_OFF + w * 16 * AP_STRIDE;

    float o[16][4];
#pragma unroll
    for (int j = 0; j < 16; j++)
#pragma unroll
        for (int q = 0; q < 4; q++) o[j][q] = 0.f;
    float m0 = -1e30f, m1 = -1e30f, l0 = 0.f, l1 = 0.f;

    const int r0g = qt * 128 + w * 16 + grp;
    const int r1g = r0g + 8;

    for (int kc = 0; kc < nch; kc++) {
        if (kc + 1 < nch) { CP_WAIT(1); } else { CP_WAIT(0); }
        __syncthreads();

        const uint32_t* Ksb = smu + (kc & 1) * AK_U32;
        const uint32_t* Vsb = smu + AV_OFF + (kc & 1) * AV_U32;

        float s[8][4];
#pragma unroll
        for (int j = 0; j < 8; j++)
#pragma unroll
            for (int q = 0; q < 4; q++) s[j][q] = 0.f;

#pragma unroll
        for (int kk = 0; kk < 16; kk++) {
#pragma unroll
            for (int j = 0; j < 8; j++) {
                uint32_t b[2];
                const uint32_t* kb = Ksb + (j * 8 + grp) * AK_STRIDE + kk * 8;
                b[0] = kb[qid];
                b[1] = kb[qid + 4];
                mma_tf32(s[j], qf[kk], b);
            }
        }

        const int cbase = kc * 64;
#pragma unroll
        for (int j = 0; j < 8; j++) {
            const int c0 = cbase + j * 8 + 2 * qid;
            if (c0 > r0g)     s[j][0] = -1e30f;
            if (c0 + 1 > r0g) s[j][1] = -1e30f;
            if (c0 > r1g)     s[j][2] = -1e30f;
            if (c0 + 1 > r1g) s[j][3] = -1e30f;
        }

        float mc0 = -1e30f, mc1 = -1e30f;
#pragma unroll
        for (int j = 0; j < 8; j++) {
            mc0 = fmaxf(mc0, fmaxf(s[j][0], s[j][1]));
            mc1 = fmaxf(mc1, fmaxf(s[j][2], s[j][3]));
        }
        mc0 = fmaxf(mc0, __shfl_xor_sync(0xFFFFFFFF, mc0, 1));
        mc0 = fmaxf(mc0, __shfl_xor_sync(0xFFFFFFFF, mc0, 2));
        mc1 = fmaxf(mc1, __shfl_xor_sync(0xFFFFFFFF, mc1, 1));
        mc1 = fmaxf(mc1, __shfl_xor_sync(0xFFFFFFFF, mc1, 2));

        const float mn0 = fmaxf(m0, mc0);
        const float mn1 = fmaxf(m1, mc1);
        const float corr0 = __expf(m0 - mn0);
        const float corr1 = __expf(m1 - mn1);
        m0 = mn0; m1 = mn1;

        float ls0 = 0.f, ls1 = 0.f;
#pragma unroll
        for (int j = 0; j < 8; j++) {
            s[j][0] = __expf(s[j][0] - mn0);
            s[j][1] = __expf(s[j][1] - mn0);
            s[j][2] = __expf(s[j][2] - mn1);
            s[j][3] = __expf(s[j][3] - mn1);
            ls0 += s[j][0] + s[j][1];
            ls1 += s[j][2] + s[j][3];
        }
        ls0 += __shfl_xor_sync(0xFFFFFFFF, ls0, 1);
        ls0 += __shfl_xor_sync(0xFFFFFFFF, ls0, 2);
        ls1 += __shfl_xor_sync(0xFFFFFFFF, ls1, 1);
        ls1 += __shfl_xor_sync(0xFFFFFFFF, ls1, 2);
        l0 = l0 * corr0 + ls0;
        l1 = l1 * corr1 + ls1;

#pragma unroll
        for (int j = 0; j < 16; j++) {
            o[j][0] *= corr0; o[j][1] *= corr0;
            o[j][2] *= corr1; o[j][3] *= corr1;
        }

#pragma unroll
        for (int j = 0; j < 8; j++) {
            uint32_t* p0 = Pw + grp * AP_STRIDE + j * 8 + 2 * qid;
            p0[0] = f2tf32(s[j][0]);
            p0[1] = f2tf32(s[j][1]);
            uint32_t* p1 = p0 + 8 * AP_STRIDE;
            p1[0] = f2tf32(s[j][2]);
            p1[1] = f2tf32(s[j][3]);
        }
        __syncwarp();

#pragma unroll
        for (int kk = 0; kk < 8; kk++) {
            uint32_t a[4];
            const uint32_t* pb = Pw + grp * AP_STRIDE + kk * 8;
            a[0] = pb[qid];
            a[1] = pb[8 * AP_STRIDE + qid];
            a[2] = pb[qid + 4];
            a[3] = pb[8 * AP_STRIDE + qid + 4];
#pragma unroll
            for (int j = 0; j < 16; j++) {
                uint32_t b[2];
                const uint32_t* vb = Vsb + (kk * 8 + qid) * AV_STRIDE + j * 8 + grp;
                b[0] = vb[0];
                b[1] = vb[4 * AV_STRIDE];
                mma_tf32(o[j], a, b);
            }
        }

        __syncthreads();
        if (kc + 2 < nch) issue_kv(kc + 2, kc & 1);
    }

    const float inv0 = 1.f / l0;
    const float inv1 = 1.f / l1;
    const int b = bh >> 4, h = bh & 15;
    float* y0 = Y + ((size_t)(b * SEQ_ + r0g)) * DIM_ + h * HD_;
    float* y1 = Y + ((size_t)(b * SEQ_ + r1g)) * DIM_ + h * HD_;
#pragma unroll
    for (int j = 0; j < 16; j++) {
        const int col = j * 8 + 2 * qid;
        *(float2*)(y0 + col) = make_float2(tf32r(o[j][0] * inv0), tf32r(o[j][1] * inv0));
        *(float2*)(y1 + col) = make_float2(tf32r(o[j][2] * inv1), tf32r(o[j][3] * inv1));
    }
}

// ============================================================
// launch
// ============================================================
extern "C" void kernel_launch(void* const* d_in, const int* in_sizes, int n_in,
                              void* d_out, int out_size)
{
    const float* x    = (const float*)d_in[0];
    const float* Wqkv = (const float*)d_in[1];
    const float* Wout = (const float*)d_in[2];
    float* out = (float*)d_out;

    float *qkv, *Q, *K, *V, *Y, *xr, *wqkvt, *woutt;
    cudaGetSymbolAddress((void**)&qkv, g_qkv);
    cudaGetSymbolAddress((void**)&Q, g_q);
    cudaGetSymbolAddress((void**)&K, g_k);
    cudaGetSymbolAddress((void**)&V, g_v);
    cudaGetSymbolAddress((void**)&Y, g_y);
    cudaGetSymbolAddress((void**)&xr, g_xr);
    cudaGetSymbolAddress((void**)&wqkvt, g_wqkvt);
    cudaGetSymbolAddress((void**)&woutt, g_woutt);

    cudaFuncSetAttribute(tf32_gemm_ldsm, cudaFuncAttributeMaxDynamicSharedMemorySize, GEMM_SMEM_BYTES);
    cudaFuncSetAttribute(attn_mma_kernel, cudaFuncAttributeMaxDynamicSharedMemorySize, ATT_SMEM_BYTES);

    // 0) tf32-round x; round+transpose weights to [N][K]
    round_x_kernel<<<(N4_X + 255) / 256, 256>>>((const float4*)x, (float4*)xr, N4_X);
    transpose_round_kernel<<<dim3(QKVN_ / 32, DIM_ / 32), dim3(32, 8)>>>(Wqkv, wqkvt, DIM_, QKVN_);
    transpose_round_kernel<<<dim3(DIM_ / 32, DIM_ / 32), dim3(32, 8)>>>(Wout, woutt, DIM_, DIM_);

    // 1) qkv = x @ Wqkv  (A [M][K], Bt [N][K], ldmatrix GEMM)
    tf32_gemm_ldsm<<<dim3(QKVN_ / 128, ROWS_ / 128), 256, GEMM_SMEM_BYTES>>>(xr, wqkvt, qkv, ROWS_, QKVN_, DIM_);

    // 2) split + rope (+ scale folded into Q), outputs tf32-rounded
    rope_split_kernel<<<(BATCH_ * NH_ * SEQ_ * HD_) / 256, 256>>>(qkv, Q, K, V);

    // 3) causal attention -> Y (tf32-rounded)
    attn_mma_kernel<<<dim3(SEQ_ / 128, BATCH_ * NH_), 256, ATT_SMEM_BYTES>>>(Q, K, V, Y);

    // 4) out = Y @ Wout
    tf32_gemm_ldsm<<<dim3(DIM_ / 128, ROWS_ / 128), 256, GEMM_SMEM_BYTES>>>(Y, woutt, out, ROWS_, DIM_, DIM_);
}

// round 12
// speedup vs baseline: 1.1237x; 1.0245x over previous
#include <cuda_runtime.h>
#include <math.h>
#include <cstdint>

#define BATCH_ 16
#define SEQ_ 512
#define DIM_ 2048
#define NH_ 16
#define HD_ 128
#define ROWS_ (BATCH_*SEQ_)    // 8192
#define QKVN_ (3*DIM_)         // 6144

// ---- scratch (static device globals; no runtime allocation) ----
__device__ float g_q[(size_t)BATCH_*NH_*SEQ_*HD_];
__device__ float g_k[(size_t)BATCH_*NH_*SEQ_*HD_];
__device__ float g_v[(size_t)BATCH_*NH_*SEQ_*HD_];
__device__ float g_y[(size_t)ROWS_ * DIM_];
__device__ float g_xr[(size_t)ROWS_ * DIM_];       // tf32-rounded x
__device__ float g_wqkvt[(size_t)DIM_ * QKVN_];    // Wqkv^T [6144][2048], tf32
__device__ float g_woutt[(size_t)DIM_ * DIM_];     // Wout^T [2048][2048], tf32

extern __shared__ char dyn_smem[];

// ============================================================
// helpers
// ============================================================
__device__ __forceinline__ uint32_t f2tf32(float f) {
    uint32_t r;
    asm("cvt.rna.tf32.f32 %0, %1;" : "=r"(r) : "f"(f));
    return r;
}
__device__ __forceinline__ float tf32r(float f) { return __uint_as_float(f2tf32(f)); }

__device__ __forceinline__ void mma_tf32(float* c, const uint32_t* a, const uint32_t* b) {
    asm volatile(
        "mma.sync.aligned.m16n8k8.row.col.f32.tf32.tf32.f32 "
        "{%0,%1,%2,%3}, {%4,%5,%6,%7}, {%8,%9}, {%0,%1,%2,%3};"
        : "+f"(c[0]), "+f"(c[1]), "+f"(c[2]), "+f"(c[3])
        : "r"(a[0]), "r"(a[1]), "r"(a[2]), "r"(a[3]), "r"(b[0]), "r"(b[1]));
}

__device__ __forceinline__ void ldsm_x4(uint32_t* r, uint32_t addr) {
    asm volatile("ldmatrix.sync.aligned.m8n8.x4.shared.b16 {%0,%1,%2,%3}, [%4];"
        : "=r"(r[0]), "=r"(r[1]), "=r"(r[2]), "=r"(r[3]) : "r"(addr));
}

__device__ __forceinline__ uint32_t smem_u32(const void* p) {
    uint32_t a;
    asm("{ .reg .u64 t; cvta.to.shared.u64 t, %1; cvt.u32.u64 %0, t; }" : "=r"(a) : "l"(p));
    return a;
}
__device__ __forceinline__ void cp16(uint32_t dst, const void* src) {
    asm volatile("cp.async.cg.shared.global [%0], [%1], 16;" :: "r"(dst), "l"(src) : "memory");
}
#define CP_COMMIT() asm volatile("cp.async.commit_group;" ::: "memory")
#define CP_WAIT(n)  asm volatile("cp.async.wait_group %0;" :: "n"(n) : "memory")

// ============================================================
// x rounding (elementwise) + fused round+transpose for weights
// ============================================================
#define N4_X (ROWS_*DIM_/4)

__global__ __launch_bounds__(256) void round_x_kernel(
    const float4* __restrict__ in, float4* __restrict__ out, int n4)
{
    int i = blockIdx.x * blockDim.x + threadIdx.x;
    if (i < n4) {
        float4 v = in[i];
        v.x = tf32r(v.x); v.y = tf32r(v.y); v.z = tf32r(v.z); v.w = tf32r(v.w);
        out[i] = v;
    }
}

// out[c][r] = tf32r(in[r][c]);  in: [R][C].  grid (C/32, R/32), block (32,8)
__global__ __launch_bounds__(256) void transpose_round_kernel(
    const float* __restrict__ in, float* __restrict__ out, int R, int C)
{
    __shared__ float t[32][33];
    const int bx = blockIdx.x * 32, by = blockIdx.y * 32;
    const int tx = threadIdx.x, ty = threadIdx.y;
#pragma unroll
    for (int i = 0; i < 4; i++)
        t[ty + i * 8][tx] = tf32r(in[(size_t)(by + ty + i * 8) * C + bx + tx]);
    __syncthreads();
#pragma unroll
    for (int i = 0; i < 4; i++)
        out[(size_t)(bx + ty + i * 8) * R + by + tx] = t[tx][ty + i * 8];
}

// ============================================================
// GEMM shared core config (ldmatrix, 128x128, BK=32, 3-stage)
// ============================================================
#define GK_STRIDE 36
#define GT_U32 (128 * GK_STRIDE)
#define GSTAGE_U32 (2 * GT_U32)
#define GEMM_SMEM_BYTES (3 * GSTAGE_U32 * 4)   // 110592 -> 2 CTAs/SM

// mainloop macro body shared by both GEMM kernels (identical math)
#define GEMM_MAINLOOP(Ab, Bb, Kdim)                                                   \
    const int nch = (Kdim) / 32;                                                      \
    auto issue = [&](int ch, int s) {                                                 \
        const uint32_t sa = sbase + (uint32_t)(s * GSTAGE_U32) * 4;                   \
        const uint32_t sb = sa + GT_U32 * 4;                                          \
        _Pragma("unroll")                                                             \
        for (int i = 0; i < 4; i++) {                                                 \
            int cidx = tid + i * 256;                                                 \
            int r = cidx >> 3, c4 = cidx & 7;                                         \
            uint32_t off = (uint32_t)(r * GK_STRIDE + c4 * 4) * 4;                    \
            cp16(sa + off, (Ab) + (size_t)r * (Kdim) + ch * 32 + c4 * 4);             \
            cp16(sb + off, (Bb) + (size_t)r * (Kdim) + ch * 32 + c4 * 4);             \
        }                                                                             \
        CP_COMMIT();                                                                  \
    };                                                                                \
    float c[4][4][4];                                                                 \
    _Pragma("unroll")                                                                 \
    for (int i = 0; i < 4; i++)                                                       \
        _Pragma("unroll")                                                             \
        for (int j = 0; j < 4; j++)                                                   \
            _Pragma("unroll")                                                         \
            for (int q = 0; q < 4; q++) c[i][j][q] = 0.f;                             \
    issue(0, 0);                                                                      \
    issue(1, 1);                                                                      \
    for (int ch = 0; ch < nch; ch++) {                                                \
        if (ch + 1 < nch) { CP_WAIT(1); } else { CP_WAIT(0); }                        \
        __syncthreads();                                                              \
        const uint32_t abase = sbase + (uint32_t)((ch % 3) * GSTAGE_U32) * 4;         \
        const uint32_t bbase = abase + GT_U32 * 4;                                    \
        _Pragma("unroll")                                                             \
        for (int ks = 0; ks < 4; ks++) {                                              \
            const int kk = ks * 8;                                                    \
            uint32_t af[4][4], bf[4][2];                                              \
            _Pragma("unroll")                                                         \
            for (int i = 0; i < 4; i++)                                               \
                ldsm_x4(af[i], abase + (uint32_t)((wm + i * 16 + a_r) * GK_STRIDE + kk + a_c) * 4); \
            _Pragma("unroll")                                                         \
            for (int j2 = 0; j2 < 2; j2++) {                                          \
                uint32_t r4[4];                                                       \
                ldsm_x4(r4, bbase + (uint32_t)((wn + j2 * 16 + b_r) * GK_STRIDE + kk + b_c) * 4);   \
                bf[2 * j2][0] = r4[0]; bf[2 * j2][1] = r4[1];                         \
                bf[2 * j2 + 1][0] = r4[2]; bf[2 * j2 + 1][1] = r4[3];                 \
            }                                                                         \
            _Pragma("unroll")                                                         \
            for (int i = 0; i < 4; i++)                                               \
                _Pragma("unroll")                                                     \
                for (int j = 0; j < 4; j++)                                           \
                    mma_tf32(c[i][j], af[i], bf[j]);                                  \
        }                                                                             \
        if (ch + 2 < nch) issue(ch + 2, (ch + 2) % 3);                                \
    }

// ============================================================
// GEMM1 fused: qkv-projection + RoPE + split + scale.
// A = xr [8192][2048], Bt = wqkvt [6144][2048].
// grid (48, 64): bn<16 q-head, bn<32 k-head, else v-head.
// Epilogue applies RoPE (pairs live in the same thread: j=0 <-> j=1),
// scales q by 1/sqrt(hd), rounds tf32, writes [B,H,T,hd].
// ============================================================
__global__ __launch_bounds__(256) void gemm_qkv_rope(
    const float* __restrict__ A, const float* __restrict__ Bt,
    float* __restrict__ Q, float* __restrict__ Kd, float* __restrict__ V)
{
    const uint32_t sbase = smem_u32(dyn_smem);
    const int tid = threadIdx.x;
    const int lane = tid & 31;
    const int w = tid >> 5;
    const int wm = (w & 1) * 64;
    const int wn = (w >> 1) * 32;
    const int grp = lane >> 2;
    const int qid = lane & 3;
    const int a_r = (lane & 7) + ((lane >> 3) & 1) * 8;
    const int a_c = (lane >> 4) * 4;
    const int b_r = (lane & 7) + (lane >> 4) * 8;
    const int b_c = ((lane >> 3) & 1) * 4;

    const int bm = blockIdx.y, bn = blockIdx.x;
    const float* Ab = A + (size_t)bm * 128 * DIM_;
    const float* Bb = Bt + (size_t)bn * 128 * DIM_;

    GEMM_MAINLOOP(Ab, Bb, DIM_)

    // ---- fused epilogue ----
    const int htype = bn >> 4;           // 0=q, 1=k, 2=v
    const int h = bn & 15;
    float* dst = (htype == 0) ? Q : (htype == 1) ? Kd : V;
    const float scale = (htype == 0) ? 0.08838834764831845f : 1.0f;

#pragma unroll
    for (int i = 0; i < 4; i++) {
        const int grow = bm * 128 + wm + i * 16 + grp;   // global row (b*SEQ+t)
        const int b = grow >> 9;
        const int t0 = grow & 511;

        if (htype < 2 && wn == 0) {
            // RoPE on dims 0..15: this thread's j=0 (d) pairs with j=1 (d+8)
#pragma unroll
            for (int q4 = 0; q4 < 4; q4++) {
                const int d = qid * 2 + (q4 & 1);
                const int t = t0 + (q4 >> 1) * 8;
                float inv = expf(-(float)d * (9.210340371976184f / 8.0f));
                float sn, cs;
                sincosf((float)t * inv, &sn, &cs);
                float x1 = c[i][0][q4];
                float x2 = c[i][1][q4];
                c[i][0][q4] = x1 * cs - x2 * sn;
                c[i][1][q4] = x2 * cs + x1 * sn;
            }
        }

        const size_t base0 = ((size_t)((b * NH_ + h) * SEQ_) + t0) * HD_;
#pragma unroll
        for (int j = 0; j < 4; j++) {
            const int col = wn + j * 8 + qid * 2;
            *(float2*)(dst + base0 + col) =
                make_float2(tf32r(c[i][j][0] * scale), tf32r(c[i][j][1] * scale));
            *(float2*)(dst + base0 + 8 * HD_ + col) =
                make_float2(tf32r(c[i][j][2] * scale), tf32r(c[i][j][3] * scale));
        }
    }
}

// ============================================================
// GEMM2 (generic): C[M,N] = A[M,K] @ Bt[N,K]^T.
// ============================================================
__global__ __launch_bounds__(256) void tf32_gemm_ldsm(
    const float* __restrict__ A, const float* __restrict__ Bt,
    float* __restrict__ C, int M, int N, int K)
{
    const uint32_t sbase = smem_u32(dyn_smem);
    const int tid = threadIdx.x;
    const int lane = tid & 31;
    const int w = tid >> 5;
    const int wm = (w & 1) * 64;
    const int wn = (w >> 1) * 32;
    const int grp = lane >> 2;
    const int qid = lane & 3;
    const int a_r = (lane & 7) + ((lane >> 3) & 1) * 8;
    const int a_c = (lane >> 4) * 4;
    const int b_r = (lane & 7) + (lane >> 4) * 8;
    const int b_c = ((lane >> 3) & 1) * 4;

    const int bm = blockIdx.y, bn = blockIdx.x;
    const float* Ab = A + (size_t)bm * 128 * K;
    const float* Bb = Bt + (size_t)bn * 128 * K;

    GEMM_MAINLOOP(Ab, Bb, K)

#pragma unroll
    for (int i = 0; i < 4; i++) {
        const int row = bm * 128 + wm + i * 16 + grp;
#pragma unroll
        for (int j = 0; j < 4; j++) {
            const int col = bn * 128 + wn + j * 8 + qid * 2;
            *(float2*)(C + (size_t)row * N + col)       = make_float2(c[i][j][0], c[i][j][1]);
            *(float2*)(C + (size_t)(row + 8) * N + col) = make_float2(c[i][j][2], c[i][j][3]);
        }
    }
}

// ============================================================
// Tensor-core flash attention v3 (unchanged; measured 179 us).
// ============================================================
#define AK_STRIDE 132
#define AV_STRIDE 136
#define AP_STRIDE 76
#define AK_U32 (64 * AK_STRIDE)
#define AV_U32 (64 * AV_STRIDE)
#define AV_OFF (2 * AK_U32)
#define AP_OFF (AV_OFF + 2 * AV_U32)
#define ATT_SMEM_BYTES ((AP_OFF + 8 * 16 * AP_STRIDE) * 4)

__global__ __launch_bounds__(256, 1) void attn_mma_kernel(
    const float* __restrict__ Q, const float* __restrict__ K,
    const float* __restrict__ V, float* __restrict__ Y)
{
    const uint32_t sbase = smem_u32(dyn_smem);
    uint32_t* smu = (uint32_t*)dyn_smem;

    const int qt = blockIdx.x, bh = blockIdx.y;
    const int tid = threadIdx.x;
    const int lane = tid & 31;
    const int w = tid >> 5;
    const int grp = lane >> 2;
    const int qid = lane & 3;

    const float* Qh = Q + (size_t)bh * SEQ_ * HD_ + (size_t)qt * 128 * HD_;
    const float* Kh = K + (size_t)bh * SEQ_ * HD_;
    const float* Vh = V + (size_t)bh * SEQ_ * HD_;

    const int nch = 2 * qt + 2;

    uint32_t qf[16][4];
    {
#pragma unroll
        for (int i = 0; i < 16; i++) {
            int idx = tid + i * 256;
            int r = idx >> 5, c4 = idx & 31;
            cp16(sbase + (uint32_t)(r * AK_STRIDE + c4 * 4) * 4,
                 Qh + (size_t)r * HD_ + c4 * 4);
        }
        CP_COMMIT();
        CP_WAIT(0);
        __syncthreads();
        const int qrow = w * 16 + grp;
#pragma unroll
        for (int kk = 0; kk < 16; kk++) {
            const uint32_t* qb = smu + qrow * AK_STRIDE + kk * 8;
            qf[kk][0] = qb[qid];
            qf[kk][1] = qb[8 * AK_STRIDE + qid];
            qf[kk][2] = qb[qid + 4];
            qf[kk][3] = qb[8 * AK_STRIDE + qid + 4];
        }
        __syncthreads();
    }

    auto issue_kv = [&](int kc, int s) {
        const uint32_t ks = sbase + (uint32_t)(s * AK_U32) * 4;
        const uint32_t vs = sbase + (uint32_t)(AV_OFF + s * AV_U32) * 4;
#pragma unroll
        for (int i = 0; i < 8; i++) {
            int cidx = tid + i * 256;
            int r = cidx >> 5, c4 = cidx & 31;
            cp16(ks + (uint32_t)(r * AK_STRIDE + c4 * 4) * 4,
                 Kh + (size_t)(kc * 64 + r) * HD_ + c4 * 4);
            cp16(vs + (uint32_t)(r * AV_STRIDE + c4 * 4) * 4,
                 Vh + (size_t)(kc * 64 + r) * HD_ + c4 * 4);
        }
        CP_COMMIT();
    };

    issue_kv(0, 0);
    issue_kv(1, 1);

    uint32_t* Pw = smu + AP_OFF + w * 16 * AP_STRIDE;

    float o[16][4];
#pragma unroll
    for (int j = 0; j < 16; j++)
#pragma unroll
        for (int q = 0; q < 4; q++) o[j][q] = 0.f;
    float m0 = -1e30f, m1 = -1e30f, l0 = 0.f, l1 = 0.f;

    const int r0g = qt * 128 + w * 16 + grp;
    const int r1g = r0g + 8;

    for (int kc = 0; kc < nch; kc++) {
        if (kc + 1 < nch) { CP_WAIT(1); } else { CP_WAIT(0); }
        __syncthreads();

        const uint32_t* Ksb = smu + (kc & 1) * AK_U32;
        const uint32_t* Vsb = smu + AV_OFF + (kc & 1) * AV_U32;

        float s[8][4];
#pragma unroll
        for (int j = 0; j < 8; j++)
#pragma unroll
            for (int q = 0; q < 4; q++) s[j][q] = 0.f;

#pragma unroll
        for (int kk = 0; kk < 16; kk++) {
#pragma unroll
            for (int j = 0; j < 8; j++) {
                uint32_t b[2];
                const uint32_t* kb = Ksb + (j * 8 + grp) * AK_STRIDE + kk * 8;
                b[0] = kb[qid];
                b[1] = kb[qid + 4];
                mma_tf32(s[j], qf[kk], b);
            }
        }

        const int cbase = kc * 64;
#pragma unroll
        for (int j = 0; j < 8; j++) {
            const int c0 = cbase + j * 8 + 2 * qid;
            if (c0 > r0g)     s[j][0] = -1e30f;
            if (c0 + 1 > r0g) s[j][1] = -1e30f;
            if (c0 > r1g)     s[j][2] = -1e30f;
            if (c0 + 1 > r1g) s[j][3] = -1e30f;
        }

        float mc0 = -1e30f, mc1 = -1e30f;
#pragma unroll
        for (int j = 0; j < 8; j++) {
            mc0 = fmaxf(mc0, fmaxf(s[j][0], s[j][1]));
            mc1 = fmaxf(mc1, fmaxf(s[j][2], s[j][3]));
        }
        mc0 = fmaxf(mc0, __shfl_xor_sync(0xFFFFFFFF, mc0, 1));
        mc0 = fmaxf(mc0, __shfl_xor_sync(0xFFFFFFFF, mc0, 2));
        mc1 = fmaxf(mc1, __shfl_xor_sync(0xFFFFFFFF, mc1, 1));
        mc1 = fmaxf(mc1, __shfl_xor_sync(0xFFFFFFFF, mc1, 2));

        const float mn0 = fmaxf(m0, mc0);
        const float mn1 = fmaxf(m1, mc1);
        const float corr0 = __expf(m0 - mn0);
        const float corr1 = __expf(m1 - mn1);
        m0 = mn0; m1 = mn1;

        float ls0 = 0.f, ls1 = 0.f;
#pragma unroll
        for (int j = 0; j < 8; j++) {
            s[j][0] = __expf(s[j][0] - mn0);
            s[j][1] = __expf(s[j][1] - mn0);
            s[j][2] = __expf(s[j][2] - mn1);
            s[j][3] = __expf(s[j][3] - mn1);
            ls0 += s[j][0] + s[j][1];
            ls1 += s[j][2] + s[j][3];
        }
        ls0 += __shfl_xor_sync(0xFFFFFFFF, ls0, 1);
        ls0 += __shfl_xor_sync(0xFFFFFFFF, ls0, 2);
        ls1 += __shfl_xor_sync(0xFFFFFFFF, ls1, 1);
        ls1 += __shfl_xor_sync(0xFFFFFFFF, ls1, 2);
        l0 = l0 * corr0 + ls0;
        l1 = l1 * corr1 + ls1;

#pragma unroll
        for (int j = 0; j < 16; j++) {
            o[j][0] *= corr0; o[j][1] *= corr0;
            o[j][2] *= corr1; o[j][3] *= corr1;
        }

#pragma unroll
        for (int j = 0; j < 8; j++) {
            uint32_t* p0 = Pw + grp * AP_STRIDE + j * 8 + 2 * qid;
            p0[0] = f2tf32(s[j][0]);
            p0[1] = f2tf32(s[j][1]);
            uint32_t* p1 = p0 + 8 * AP_STRIDE;
            p1[0] = f2tf32(s[j][2]);
            p1[1] = f2tf32(s[j][3]);
        }
        __syncwarp();

#pragma unroll
        for (int kk = 0; kk < 8; kk++) {
            uint32_t a[4];
            const uint32_t* pb = Pw + grp * AP_STRIDE + kk * 8;
            a[0] = pb[qid];
            a[1] = pb[8 * AP_STRIDE + qid];
            a[2] = pb[qid + 4];
            a[3] = pb[8 * AP_STRIDE + qid + 4];
#pragma unroll
            for (int j = 0; j < 16; j++) {
                uint32_t b[2];
                const uint32_t* vb = Vsb + (kk * 8 + qid) * AV_STRIDE + j * 8 + grp;
                b[0] = vb[0];
                b[1] = vb[4 * AV_STRIDE];
                mma_tf32(o[j], a, b);
            }
        }

        __syncthreads();
        if (kc + 2 < nch) issue_kv(kc + 2, kc & 1);
    }

    const float inv0 = 1.f / l0;
    const float inv1 = 1.f / l1;
    const int b = bh >> 4, h = bh & 15;
    float* y0 = Y + ((size_t)(b * SEQ_ + r0g)) * DIM_ + h * HD_;
    float* y1 = Y + ((size_t)(b * SEQ_ + r1g)) * DIM_ + h * HD_;
#pragma unroll
    for (int j = 0; j < 16; j++) {
        const int col = j * 8 + 2 * qid;
        *(float2*)(y0 + col) = make_float2(tf32r(o[j][0] * inv0), tf32r(o[j][1] * inv0));
        *(float2*)(y1 + col) = make_float2(tf32r(o[j][2] * inv1), tf32r(o[j][3] * inv1));
    }
}

// ============================================================
// launch
// ============================================================
extern "C" void kernel_launch(void* const* d_in, const int* in_sizes, int n_in,
                              void* d_out, int out_size)
{
    const float* x    = (const float*)d_in[0];
    const float* Wqkv = (const float*)d_in[1];
    const float* Wout = (const float*)d_in[2];
    float* out = (float*)d_out;

    float *Q, *K, *V, *Y, *xr, *wqkvt, *woutt;
    cudaGetSymbolAddress((void**)&Q, g_q);
    cudaGetSymbolAddress((void**)&K, g_k);
    cudaGetSymbolAddress((void**)&V, g_v);
    cudaGetSymbolAddress((void**)&Y, g_y);
    cudaGetSymbolAddress((void**)&xr, g_xr);
    cudaGetSymbolAddress((void**)&wqkvt, g_wqkvt);
    cudaGetSymbolAddress((void**)&woutt, g_woutt);

    cudaFuncSetAttribute(gemm_qkv_rope, cudaFuncAttributeMaxDynamicSharedMemorySize, GEMM_SMEM_BYTES);
    cudaFuncSetAttribute(tf32_gemm_ldsm, cudaFuncAttributeMaxDynamicSharedMemorySize, GEMM_SMEM_BYTES);
    cudaFuncSetAttribute(attn_mma_kernel, cudaFuncAttributeMaxDynamicSharedMemorySize, ATT_SMEM_BYTES);

    // 0) tf32-round x; round+transpose weights to [N][K]
    round_x_kernel<<<(N4_X + 255) / 256, 256>>>((const float4*)x, (float4*)xr, N4_X);
    transpose_round_kernel<<<dim3(QKVN_ / 32, DIM_ / 32), dim3(32, 8)>>>(Wqkv, wqkvt, DIM_, QKVN_);
    transpose_round_kernel<<<dim3(DIM_ / 32, DIM_ / 32), dim3(32, 8)>>>(Wout, woutt, DIM_, DIM_);

    // 1) fused qkv-projection + RoPE + split + scale -> Q,K,V [B,H,T,hd]
    gemm_qkv_rope<<<dim3(QKVN_ / 128, ROWS_ / 128), 256, GEMM_SMEM_BYTES>>>(xr, wqkvt, Q, K, V);

    // 2) causal attention -> Y (tf32-rounded, (B,T,C) layout)
    attn_mma_kernel<<<dim3(SEQ_ / 128, BATCH_ * NH_), 256, ATT_SMEM_BYTES>>>(Q, K, V, Y);

    // 3) out = Y @ Wout
    tf32_gemm_ldsm<<<dim3(DIM_ / 128, ROWS_ / 128), 256, GEMM_SMEM_BYTES>>>(Y, woutt, out, ROWS_, DIM_, DIM_);
}

// round 13
// speedup vs baseline: 1.1338x; 1.0091x over previous
#include <cuda_runtime.h>
#include <math.h>
#include <cstdint>

#define BATCH_ 16
#define SEQ_ 512
#define DIM_ 2048
#define NH_ 16
#define HD_ 128
#define ROWS_ (BATCH_*SEQ_)    // 8192
#define QKVN_ (3*DIM_)         // 6144

// ---- scratch (static device globals; no runtime allocation) ----
__device__ float g_q[(size_t)BATCH_*NH_*SEQ_*HD_];
__device__ float g_k[(size_t)BATCH_*NH_*SEQ_*HD_];
__device__ float g_v[(size_t)BATCH_*NH_*SEQ_*HD_];
__device__ float g_y[(size_t)ROWS_ * DIM_];
__device__ float g_xr[(size_t)ROWS_ * DIM_];       // tf32-rounded x
__device__ float g_wqkvt[(size_t)DIM_ * QKVN_];    // Wqkv^T [6144][2048], tf32
__device__ float g_woutt[(size_t)DIM_ * DIM_];     // Wout^T [2048][2048], tf32

extern __shared__ char dyn_smem[];

// ============================================================
// helpers
// ============================================================
__device__ __forceinline__ uint32_t f2tf32(float f) {
    uint32_t r;
    asm("cvt.rna.tf32.f32 %0, %1;" : "=r"(r) : "f"(f));
    return r;
}
__device__ __forceinline__ float tf32r(float f) { return __uint_as_float(f2tf32(f)); }

__device__ __forceinline__ void mma_tf32(float* c, const uint32_t* a, const uint32_t* b) {
    asm volatile(
        "mma.sync.aligned.m16n8k8.row.col.f32.tf32.tf32.f32 "
        "{%0,%1,%2,%3}, {%4,%5,%6,%7}, {%8,%9}, {%0,%1,%2,%3};"
        : "+f"(c[0]), "+f"(c[1]), "+f"(c[2]), "+f"(c[3])
        : "r"(a[0]), "r"(a[1]), "r"(a[2]), "r"(a[3]), "r"(b[0]), "r"(b[1]));
}

__device__ __forceinline__ void ldsm_x4(uint32_t* r, uint32_t addr) {
    asm volatile("ldmatrix.sync.aligned.m8n8.x4.shared.b16 {%0,%1,%2,%3}, [%4];"
        : "=r"(r[0]), "=r"(r[1]), "=r"(r[2]), "=r"(r[3]) : "r"(addr));
}

__device__ __forceinline__ uint32_t smem_u32(const void* p) {
    uint32_t a;
    asm("{ .reg .u64 t; cvta.to.shared.u64 t, %1; cvt.u32.u64 %0, t; }" : "=r"(a) : "l"(p));
    return a;
}
__device__ __forceinline__ void cp16(uint32_t dst, const void* src) {
    asm volatile("cp.async.cg.shared.global [%0], [%1], 16;" :: "r"(dst), "l"(src) : "memory");
}
#define CP_COMMIT() asm volatile("cp.async.commit_group;" ::: "memory")
#define CP_WAIT(n)  asm volatile("cp.async.wait_group %0;" :: "n"(n) : "memory")

// ============================================================
// x rounding (elementwise) + fused round+transpose for weights
// ============================================================
#define N4_X (ROWS_*DIM_/4)

__global__ __launch_bounds__(256) void round_x_kernel(
    const float4* __restrict__ in, float4* __restrict__ out, int n4)
{
    int i = blockIdx.x * blockDim.x + threadIdx.x;
    if (i < n4) {
        float4 v = in[i];
        v.x = tf32r(v.x); v.y = tf32r(v.y); v.z = tf32r(v.z); v.w = tf32r(v.w);
        out[i] = v;
    }
}

// out[c][r] = tf32r(in[r][c]);  in: [R][C].  grid (C/32, R/32), block (32,8)
__global__ __launch_bounds__(256) void transpose_round_kernel(
    const float* __restrict__ in, float* __restrict__ out, int R, int C)
{
    __shared__ float t[32][33];
    const int bx = blockIdx.x * 32, by = blockIdx.y * 32;
    const int tx = threadIdx.x, ty = threadIdx.y;
#pragma unroll
    for (int i = 0; i < 4; i++)
        t[ty + i * 8][tx] = tf32r(in[(size_t)(by + ty + i * 8) * C + bx + tx]);
    __syncthreads();
#pragma unroll
    for (int i = 0; i < 4; i++)
        out[(size_t)(bx + ty + i * 8) * R + by + tx] = t[tx][ty + i * 8];
}

// ============================================================
// GEMM core: 256x128 block tile, 512 threads (16 warps, 4x4),
// warp tile 64x32, BK=32, 3-stage cp.async, ldmatrix fragments.
// A [M][K], Bt [N][K], both K-major tf32-prerounded.
// ============================================================
#define GK_STRIDE 36
#define GA_U32 (256 * GK_STRIDE)          // 9216
#define GB_U32 (128 * GK_STRIDE)          // 4608
#define GSTAGE_U32 (GA_U32 + GB_U32)      // 13824
#define GEMM_SMEM_BYTES (3 * GSTAGE_U32 * 4)   // 165888

#define GEMM_MAINLOOP(Ab, Bb, Kdim)                                                   \
    const int nch = (Kdim) / 32;                                                      \
    auto issue = [&](int ch, int s) {                                                 \
        const uint32_t sa = sbase + (uint32_t)(s * GSTAGE_U32) * 4;                   \
        const uint32_t sb = sa + GA_U32 * 4;                                          \
        _Pragma("unroll")                                                             \
        for (int i = 0; i < 4; i++) {                                                 \
            int cidx = tid + i * 512;              /* A: 256 rows x 8 chunks */       \
            int r = cidx >> 3, c4 = cidx & 7;                                         \
            cp16(sa + (uint32_t)(r * GK_STRIDE + c4 * 4) * 4,                         \
                 (Ab) + (size_t)r * (Kdim) + ch * 32 + c4 * 4);                       \
        }                                                                             \
        _Pragma("unroll")                                                             \
        for (int i = 0; i < 2; i++) {                                                 \
            int cidx = tid + i * 512;              /* B: 128 rows x 8 chunks */       \
            int r = cidx >> 3, c4 = cidx & 7;                                         \
            cp16(sb + (uint32_t)(r * GK_STRIDE + c4 * 4) * 4,                         \
                 (Bb) + (size_t)r * (Kdim) + ch * 32 + c4 * 4);                       \
        }                                                                             \
        CP_COMMIT();                                                                  \
    };                                                                                \
    float c[4][4][4];                                                                 \
    _Pragma("unroll")                                                                 \
    for (int i = 0; i < 4; i++)                                                       \
        _Pragma("unroll")                                                             \
        for (int j = 0; j < 4; j++)                                                   \
            _Pragma("unroll")                                                         \
            for (int q = 0; q < 4; q++) c[i][j][q] = 0.f;                             \
    issue(0, 0);                                                                      \
    issue(1, 1);                                                                      \
    for (int ch = 0; ch < nch; ch++) {                                                \
        if (ch + 1 < nch) { CP_WAIT(1); } else { CP_WAIT(0); }                        \
        __syncthreads();                                                              \
        const uint32_t abase = sbase + (uint32_t)((ch % 3) * GSTAGE_U32) * 4;         \
        const uint32_t bbase = abase + GA_U32 * 4;                                    \
        _Pragma("unroll")                                                             \
        for (int ks = 0; ks < 4; ks++) {                                              \
            const int kk = ks * 8;                                                    \
            uint32_t af[4][4], bf[4][2];                                              \
            _Pragma("unroll")                                                         \
            for (int i = 0; i < 4; i++)                                               \
                ldsm_x4(af[i], abase + (uint32_t)((wm + i * 16 + a_r) * GK_STRIDE + kk + a_c) * 4); \
            _Pragma("unroll")                                                         \
            for (int j2 = 0; j2 < 2; j2++) {                                          \
                uint32_t r4[4];                                                       \
                ldsm_x4(r4, bbase + (uint32_t)((wn + j2 * 16 + b_r) * GK_STRIDE + kk + b_c) * 4);   \
                bf[2 * j2][0] = r4[0]; bf[2 * j2][1] = r4[1];                         \
                bf[2 * j2 + 1][0] = r4[2]; bf[2 * j2 + 1][1] = r4[3];                 \
            }                                                                         \
            _Pragma("unroll")                                                         \
            for (int i = 0; i < 4; i++)                                               \
                _Pragma("unroll")                                                     \
                for (int j = 0; j < 4; j++)                                           \
                    mma_tf32(c[i][j], af[i], bf[j]);                                  \
        }                                                                             \
        if (ch + 2 < nch) issue(ch + 2, (ch + 2) % 3);                                \
    }

// ============================================================
// GEMM1 fused: qkv-projection + RoPE + split + scale.
// grid (48, 32): bn<16 q-head, <32 k-head, else v-head; bm = 256 rows.
// ============================================================
__global__ __launch_bounds__(512, 1) void gemm_qkv_rope(
    const float* __restrict__ A, const float* __restrict__ Bt,
    float* __restrict__ Q, float* __restrict__ Kd, float* __restrict__ V)
{
    const uint32_t sbase = smem_u32(dyn_smem);
    const int tid = threadIdx.x;
    const int lane = tid & 31;
    const int w = tid >> 5;
    const int wm = (w & 3) * 64;
    const int wn = (w >> 2) * 32;
    const int grp = lane >> 2;
    const int qid = lane & 3;
    const int a_r = (lane & 7) + ((lane >> 3) & 1) * 8;
    const int a_c = (lane >> 4) * 4;
    const int b_r = (lane & 7) + (lane >> 4) * 8;
    const int b_c = ((lane >> 3) & 1) * 4;

    const int bm = blockIdx.y, bn = blockIdx.x;
    const float* Ab = A + (size_t)bm * 256 * DIM_;
    const float* Bb = Bt + (size_t)bn * 128 * DIM_;

    GEMM_MAINLOOP(Ab, Bb, DIM_)

    // ---- fused epilogue ----
    const int htype = bn >> 4;           // 0=q, 1=k, 2=v
    const int h = bn & 15;
    float* dst = (htype == 0) ? Q : (htype == 1) ? Kd : V;
    const float scale = (htype == 0) ? 0.08838834764831845f : 1.0f;

#pragma unroll
    for (int i = 0; i < 4; i++) {
        const int grow = bm * 256 + wm + i * 16 + grp;   // global row (b*SEQ+t)
        const int b = grow >> 9;
        const int t0 = grow & 511;

        if (htype < 2 && wn == 0) {
#pragma unroll
            for (int q4 = 0; q4 < 4; q4++) {
                const int d = qid * 2 + (q4 & 1);
                const int t = t0 + (q4 >> 1) * 8;
                float inv = expf(-(float)d * (9.210340371976184f / 8.0f));
                float sn, cs;
                sincosf((float)t * inv, &sn, &cs);
                float x1 = c[i][0][q4];
                float x2 = c[i][1][q4];
                c[i][0][q4] = x1 * cs - x2 * sn;
                c[i][1][q4] = x2 * cs + x1 * sn;
            }
        }

        const size_t base0 = ((size_t)((b * NH_ + h) * SEQ_) + t0) * HD_;
#pragma unroll
        for (int j = 0; j < 4; j++) {
            const int col = wn + j * 8 + qid * 2;
            *(float2*)(dst + base0 + col) =
                make_float2(tf32r(c[i][j][0] * scale), tf32r(c[i][j][1] * scale));
            *(float2*)(dst + base0 + 8 * HD_ + col) =
                make_float2(tf32r(c[i][j][2] * scale), tf32r(c[i][j][3] * scale));
        }
    }
}

// ============================================================
// GEMM2 (generic): C[M,N] = A[M,K] @ Bt[N,K]^T.  grid (N/128, M/256)
// ============================================================
__global__ __launch_bounds__(512, 1) void tf32_gemm_ldsm(
    const float* __restrict__ A, const float* __restrict__ Bt,
    float* __restrict__ C, int M, int N, int K)
{
    const uint32_t sbase = smem_u32(dyn_smem);
    const int tid = threadIdx.x;
    const int lane = tid & 31;
    const int w = tid >> 5;
    const int wm = (w & 3) * 64;
    const int wn = (w >> 2) * 32;
    const int grp = lane >> 2;
    const int qid = lane & 3;
    const int a_r = (lane & 7) + ((lane >> 3) & 1) * 8;
    const int a_c = (lane >> 4) * 4;
    const int b_r = (lane & 7) + (lane >> 4) * 8;
    const int b_c = ((lane >> 3) & 1) * 4;

    const int bm = blockIdx.y, bn = blockIdx.x;
    const float* Ab = A + (size_t)bm * 256 * K;
    const float* Bb = Bt + (size_t)bn * 128 * K;

    GEMM_MAINLOOP(Ab, Bb, K)

#pragma unroll
    for (int i = 0; i < 4; i++) {
        const int row = bm * 256 + wm + i * 16 + grp;
#pragma unroll
        for (int j = 0; j < 4; j++) {
            const int col = bn * 128 + wn + j * 8 + qid * 2;
            *(float2*)(C + (size_t)row * N + col)       = make_float2(c[i][j][0], c[i][j][1]);
            *(float2*)(C + (size_t)(row + 8) * N + col) = make_float2(c[i][j][2], c[i][j][3]);
        }
    }
}

// ============================================================
// Tensor-core flash attention v3 (unchanged; measured 179 us).
// ============================================================
#define AK_STRIDE 132
#define AV_STRIDE 136
#define AP_STRIDE 76
#define AK_U32 (64 * AK_STRIDE)
#define AV_U32 (64 * AV_STRIDE)
#define AV_OFF (2 * AK_U32)
#define AP_OFF (AV_OFF + 2 * AV_U32)
#define ATT_SMEM_BYTES ((AP_OFF + 8 * 16 * AP_STRIDE) * 4)

__global__ __launch_bounds__(256, 1) void attn_mma_kernel(
    const float* __restrict__ Q, const float* __restrict__ K,
    const float* __restrict__ V, float* __restrict__ Y)
{
    const uint32_t sbase = smem_u32(dyn_smem);
    uint32_t* smu = (uint32_t*)dyn_smem;

    const int qt = blockIdx.x, bh = blockIdx.y;
    const int tid = threadIdx.x;
    const int lane = tid & 31;
    const int w = tid >> 5;
    const int grp = lane >> 2;
    const int qid = lane & 3;

    const float* Qh = Q + (size_t)bh * SEQ_ * HD_ + (size_t)qt * 128 * HD_;
    const float* Kh = K + (size_t)bh * SEQ_ * HD_;
    const float* Vh = V + (size_t)bh * SEQ_ * HD_;

    const int nch = 2 * qt + 2;

    uint32_t qf[16][4];
    {
#pragma unroll
        for (int i = 0; i < 16; i++) {
            int idx = tid + i * 256;
            int r = idx >> 5, c4 = idx & 31;
            cp16(sbase + (uint32_t)(r * AK_STRIDE + c4 * 4) * 4,
                 Qh + (size_t)r * HD_ + c4 * 4);
        }
        CP_COMMIT();
        CP_WAIT(0);
        __syncthreads();
        const int qrow = w * 16 + grp;
#pragma unroll
        for (int kk = 0; kk < 16; kk++) {
            const uint32_t* qb = smu + qrow * AK_STRIDE + kk * 8;
            qf[kk][0] = qb[qid];
            qf[kk][1] = qb[8 * AK_STRIDE + qid];
            qf[kk][2] = qb[qid + 4];
            qf[kk][3] = qb[8 * AK_STRIDE + qid + 4];
        }
        __syncthreads();
    }

    auto issue_kv = [&](int kc, int s) {
        const uint32_t ks = sbase + (uint32_t)(s * AK_U32) * 4;
        const uint32_t vs = sbase + (uint32_t)(AV_OFF + s * AV_U32) * 4;
#pragma unroll
        for (int i = 0; i < 8; i++) {
            int cidx = tid + i * 256;
            int r = cidx >> 5, c4 = cidx & 31;
            cp16(ks + (uint32_t)(r * AK_STRIDE + c4 * 4) * 4,
                 Kh + (size_t)(kc * 64 + r) * HD_ + c4 * 4);
            cp16(vs + (uint32_t)(r * AV_STRIDE + c4 * 4) * 4,
                 Vh + (size_t)(kc * 64 + r) * HD_ + c4 * 4);
        }
        CP_COMMIT();
    };

    issue_kv(0, 0);
    issue_kv(1, 1);

    uint32_t* Pw = smu + AP_OFF + w * 16 * AP_STRIDE;

    float o[16][4];
#pragma unroll
    for (int j = 0; j < 16; j++)
#pragma unroll
        for (int q = 0; q < 4; q++) o[j][q] = 0.f;
    float m0 = -1e30f, m1 = -1e30f, l0 = 0.f, l1 = 0.f;

    const int r0g = qt * 128 + w * 16 + grp;
    const int r1g = r0g + 8;

    for (int kc = 0; kc < nch; kc++) {
        if (kc + 1 < nch) { CP_WAIT(1); } else { CP_WAIT(0); }
        __syncthreads();

        const uint32_t* Ksb = smu + (kc & 1) * AK_U32;
        const uint32_t* Vsb = smu + AV_OFF + (kc & 1) * AV_U32;

        float s[8][4];
#pragma unroll
        for (int j = 0; j < 8; j++)
#pragma unroll
            for (int q = 0; q < 4; q++) s[j][q] = 0.f;

#pragma unroll
        for (int kk = 0; kk < 16; kk++) {
#pragma unroll
            for (int j = 0; j < 8; j++) {
                uint32_t b[2];
                const uint32_t* kb = Ksb + (j * 8 + grp) * AK_STRIDE + kk * 8;
                b[0] = kb[qid];
                b[1] = kb[qid + 4];
                mma_tf32(s[j], qf[kk], b);
            }
        }

        const int cbase = kc * 64;
#pragma unroll
        for (int j = 0; j < 8; j++) {
            const int c0 = cbase + j * 8 + 2 * qid;
            if (c0 > r0g)     s[j][0] = -1e30f;
            if (c0 + 1 > r0g) s[j][1] = -1e30f;
            if (c0 > r1g)     s[j][2] = -1e30f;
            if (c0 + 1 > r1g) s[j][3] = -1e30f;
        }

        float mc0 = -1e30f, mc1 = -1e30f;
#pragma unroll
        for (int j = 0; j < 8; j++) {
            mc0 = fmaxf(mc0, fmaxf(s[j][0], s[j][1]));
            mc1 = fmaxf(mc1, fmaxf(s[j][2], s[j][3]));
        }
        mc0 = fmaxf(mc0, __shfl_xor_sync(0xFFFFFFFF, mc0, 1));
        mc0 = fmaxf(mc0, __shfl_xor_sync(0xFFFFFFFF, mc0, 2));
        mc1 = fmaxf(mc1, __shfl_xor_sync(0xFFFFFFFF, mc1, 1));
        mc1 = fmaxf(mc1, __shfl_xor_sync(0xFFFFFFFF, mc1, 2));

        const float mn0 = fmaxf(m0, mc0);
        const float mn1 = fmaxf(m1, mc1);
        const float corr0 = __expf(m0 - mn0);
        const float corr1 = __expf(m1 - mn1);
        m0 = mn0; m1 = mn1;

        float ls0 = 0.f, ls1 = 0.f;
#pragma unroll
        for (int j = 0; j < 8; j++) {
            s[j][0] = __expf(s[j][0] - mn0);
            s[j][1] = __expf(s[j][1] - mn0);
            s[j][2] = __expf(s[j][2] - mn1);
            s[j][3] = __expf(s[j][3] - mn1);
            ls0 += s[j][0] + s[j][1];
            ls1 += s[j][2] + s[j][3];
        }
        ls0 += __shfl_xor_sync(0xFFFFFFFF, ls0, 1);
        ls0 += __shfl_xor_sync(0xFFFFFFFF, ls0, 2);
        ls1 += __shfl_xor_sync(0xFFFFFFFF, ls1, 1);
        ls1 += __shfl_xor_sync(0xFFFFFFFF, ls1, 2);
        l0 = l0 * corr0 + ls0;
        l1 = l1 * corr1 + ls1;

#pragma unroll
        for (int j = 0; j < 16; j++) {
            o[j][0] *= corr0; o[j][1] *= corr0;
            o[j][2] *= corr1; o[j][3] *= corr1;
        }

#pragma unroll
        for (int j = 0; j < 8; j++) {
            uint32_t* p0 = Pw + grp * AP_STRIDE + j * 8 + 2 * qid;
            p0[0] = f2tf32(s[j][0]);
            p0[1] = f2tf32(s[j][1]);
            uint32_t* p1 = p0 + 8 * AP_STRIDE;
            p1[0] = f2tf32(s[j][2]);
            p1[1] = f2tf32(s[j][3]);
        }
        __syncwarp();

#pragma unroll
        for (int kk = 0; kk < 8; kk++) {
            uint32_t a[4];
            const uint32_t* pb = Pw + grp * AP_STRIDE + kk * 8;
            a[0] = pb[qid];
            a[1] = pb[8 * AP_STRIDE + qid];
            a[2] = pb[qid + 4];
            a[3] = pb[8 * AP_STRIDE + qid + 4];
#pragma unroll
            for (int j = 0; j < 16; j++) {
                uint32_t b[2];
                const uint32_t* vb = Vsb + (kk * 8 + qid) * AV_STRIDE + j * 8 + grp;
                b[0] = vb[0];
                b[1] = vb[4 * AV_STRIDE];
                mma_tf32(o[j], a, b);
            }
        }

        __syncthreads();
        if (kc + 2 < nch) issue_kv(kc + 2, kc & 1);
    }

    const float inv0 = 1.f / l0;
    const float inv1 = 1.f / l1;
    const int b = bh >> 4, h = bh & 15;
    float* y0 = Y + ((size_t)(b * SEQ_ + r0g)) * DIM_ + h * HD_;
    float* y1 = Y + ((size_t)(b * SEQ_ + r1g)) * DIM_ + h * HD_;
#pragma unroll
    for (int j = 0; j < 16; j++) {
        const int col = j * 8 + 2 * qid;
        *(float2*)(y0 + col) = make_float2(tf32r(o[j][0] * inv0), tf32r(o[j][1] * inv0));
        *(float2*)(y1 + col) = make_float2(tf32r(o[j][2] * inv1), tf32r(o[j][3] * inv1));
    }
}

// ============================================================
// launch
// ============================================================
extern "C" void kernel_launch(void* const* d_in, const int* in_sizes, int n_in,
                              void* d_out, int out_size)
{
    const float* x    = (const float*)d_in[0];
    const float* Wqkv = (const float*)d_in[1];
    const float* Wout = (const float*)d_in[2];
    float* out = (float*)d_out;

    float *Q, *K, *V, *Y, *xr, *wqkvt, *woutt;
    cudaGetSymbolAddress((void**)&Q, g_q);
    cudaGetSymbolAddress((void**)&K, g_k);
    cudaGetSymbolAddress((void**)&V, g_v);
    cudaGetSymbolAddress((void**)&Y, g_y);
    cudaGetSymbolAddress((void**)&xr, g_xr);
    cudaGetSymbolAddress((void**)&wqkvt, g_wqkvt);
    cudaGetSymbolAddress((void**)&woutt, g_woutt);

    cudaFuncSetAttribute(gemm_qkv_rope, cudaFuncAttributeMaxDynamicSharedMemorySize, GEMM_SMEM_BYTES);
    cudaFuncSetAttribute(tf32_gemm_ldsm, cudaFuncAttributeMaxDynamicSharedMemorySize, GEMM_SMEM_BYTES);
    cudaFuncSetAttribute(attn_mma_kernel, cudaFuncAttributeMaxDynamicSharedMemorySize, ATT_SMEM_BYTES);

    // 0) tf32-round x; round+transpose weights to [N][K]
    round_x_kernel<<<(N4_X + 255) / 256, 256>>>((const float4*)x, (float4*)xr, N4_X);
    transpose_round_kernel<<<dim3(QKVN_ / 32, DIM_ / 32), dim3(32, 8)>>>(Wqkv, wqkvt, DIM_, QKVN_);
    transpose_round_kernel<<<dim3(DIM_ / 32, DIM_ / 32), dim3(32, 8)>>>(Wout, woutt, DIM_, DIM_);

    // 1) fused qkv-projection + RoPE + split + scale -> Q,K,V [B,H,T,hd]
    gemm_qkv_rope<<<dim3(QKVN_ / 128, ROWS_ / 256), 512, GEMM_SMEM_BYTES>>>(xr, wqkvt, Q, K, V);

    // 2) causal attention -> Y (tf32-rounded, (B,T,C) layout)
    attn_mma_kernel<<<dim3(SEQ_ / 128, BATCH_ * NH_), 256, ATT_SMEM_BYTES>>>(Q, K, V, Y);

    // 3) out = Y @ Wout
    tf32_gemm_ldsm<<<dim3(DIM_ / 128, ROWS_ / 256), 512, GEMM_SMEM_BYTES>>>(Y, woutt, out, ROWS_, DIM_, DIM_);
}

// round 15
// speedup vs baseline: 1.6389x; 1.4455x over previous
#include <cuda_runtime.h>
#include <cuda_fp16.h>
#include <math.h>
#include <cstdint>

#define BATCH_ 16
#define SEQ_ 512
#define DIM_ 2048
#define NH_ 16
#define HD_ 128
#define ROWS_ (BATCH_*SEQ_)    // 8192
#define QKVN_ (3*DIM_)         // 6144

// ---- scratch (static device globals; no runtime allocation) ----
__device__ float  g_q[(size_t)BATCH_*NH_*SEQ_*HD_];
__device__ float  g_k[(size_t)BATCH_*NH_*SEQ_*HD_];
__device__ float  g_v[(size_t)BATCH_*NH_*SEQ_*HD_];
__device__ __half g_yh[(size_t)ROWS_ * DIM_];        // attention out, fp16, (B,T,C)
__device__ __half g_xh[(size_t)ROWS_ * DIM_];        // fp16 x
__device__ __half g_wqkvh[(size_t)DIM_ * QKVN_];     // Wqkv^T [6144][2048] fp16
__device__ __half g_wouth[(size_t)DIM_ * DIM_];      // Wout^T [2048][2048] fp16

extern __shared__ char dyn_smem[];

// ============================================================
// helpers
// ============================================================
__device__ __forceinline__ uint32_t f2tf32(float f) {
    uint32_t r;
    asm("cvt.rna.tf32.f32 %0, %1;" : "=r"(r) : "f"(f));
    return r;
}
__device__ __forceinline__ float tf32r(float f) { return __uint_as_float(f2tf32(f)); }

// tf32 mma (attention only)
__device__ __forceinline__ void mma_tf32(float* c, const uint32_t* a, const uint32_t* b) {
    asm volatile(
        "mma.sync.aligned.m16n8k8.row.col.f32.tf32.tf32.f32 "
        "{%0,%1,%2,%3}, {%4,%5,%6,%7}, {%8,%9}, {%0,%1,%2,%3};"
        : "+f"(c[0]), "+f"(c[1]), "+f"(c[2]), "+f"(c[3])
        : "r"(a[0]), "r"(a[1]), "r"(a[2]), "r"(a[3]), "r"(b[0]), "r"(b[1]));
}

// fp16 mma, fp32 accumulate (GEMMs): K=16 per instruction
__device__ __forceinline__ void mma_f16(float* c, const uint32_t* a, const uint32_t* b) {
    asm volatile(
        "mma.sync.aligned.m16n8k16.row.col.f32.f16.f16.f32 "
        "{%0,%1,%2,%3}, {%4,%5,%6,%7}, {%8,%9}, {%0,%1,%2,%3};"
        : "+f"(c[0]), "+f"(c[1]), "+f"(c[2]), "+f"(c[3])
        : "r"(a[0]), "r"(a[1]), "r"(a[2]), "r"(a[3]), "r"(b[0]), "r"(b[1]));
}

__device__ __forceinline__ void ldsm_x4(uint32_t* r, uint32_t addr) {
    asm volatile("ldmatrix.sync.aligned.m8n8.x4.shared.b16 {%0,%1,%2,%3}, [%4];"
        : "=r"(r[0]), "=r"(r[1]), "=r"(r[2]), "=r"(r[3]) : "r"(addr));
}

__device__ __forceinline__ uint32_t smem_u32(const void* p) {
    uint32_t a;
    asm("{ .reg .u64 t; cvta.to.shared.u64 t, %1; cvt.u32.u64 %0, t; }" : "=r"(a) : "l"(p));
    return a;
}
__device__ __forceinline__ void cp16(uint32_t dst, const void* src) {
    asm volatile("cp.async.cg.shared.global [%0], [%1], 16;" :: "r"(dst), "l"(src) : "memory");
}
#define CP_COMMIT() asm volatile("cp.async.commit_group;" ::: "memory")
#define CP_WAIT(n)  asm volatile("cp.async.wait_group %0;" :: "n"(n) : "memory")

// ============================================================
// fp16 conversion kernels
// ============================================================
#define N4_X (ROWS_*DIM_/4)

__global__ __launch_bounds__(256) void round_x_h(
    const float4* __restrict__ in, __half2* __restrict__ out, int n4)
{
    int i = blockIdx.x * blockDim.x + threadIdx.x;
    if (i < n4) {
        float4 v = in[i];
        out[2 * i]     = __floats2half2_rn(v.x, v.y);
        out[2 * i + 1] = __floats2half2_rn(v.z, v.w);
    }
}

// out[c][r] = half(in[r][c]);  in: [R][C] float.  grid (C/32, R/32), block (32,8)
__global__ __launch_bounds__(256) void transpose_h_kernel(
    const float* __restrict__ in, __half* __restrict__ out, int R, int C)
{
    __shared__ float t[32][33];
    const int bx = blockIdx.x * 32, by = blockIdx.y * 32;
    const int tx = threadIdx.x, ty = threadIdx.y;
#pragma unroll
    for (int i = 0; i < 4; i++)
        t[ty + i * 8][tx] = in[(size_t)(by + ty + i * 8) * C + bx + tx];
    __syncthreads();
#pragma unroll
    for (int i = 0; i < 4; i++)
        out[(size_t)(bx + ty + i * 8) * R + by + tx] = __float2half_rn(t[tx][ty + i * 8]);
}

// ============================================================
// fp16 GEMM core: 256x128 block tile, 512 threads (16 warps 4x4),
// warp tile 64x32, BK=64 halves, 3-stage cp.async, ldmatrix b16.
// A [M][K] half, Bt [N][K] half. Accumulate fp32.
// smem row stride 72 halves (144B): ldmatrix conflict-free.
// ============================================================
#define GK_STRIDE 72
#define GA_HALF (256 * GK_STRIDE)          // halves
#define GB_HALF (128 * GK_STRIDE)
#define GSTAGE_HALF (GA_HALF + GB_HALF)    // 27648 halves = 55296 B
#define GEMM_SMEM_BYTES (3 * GSTAGE_HALF * 2)   // 165888

#define GEMM_MAINLOOP_F16(Ab, Bb, Kdim)                                               \
    const int nch = (Kdim) / 64;                                                      \
    auto issue = [&](int ch, int s) {                                                 \
        const uint32_t sa = sbase + (uint32_t)(s * GSTAGE_HALF) * 2;                  \
        const uint32_t sb = sa + GA_HALF * 2;                                         \
        _Pragma("unroll")                                                             \
        for (int i = 0; i < 4; i++) {                                                 \
            int cidx = tid + i * 512;              /* A: 256 rows x 8 x 16B */        \
            int r = cidx >> 3, c8 = cidx & 7;                                         \
            cp16(sa + (uint32_t)(r * GK_STRIDE + c8 * 8) * 2,                         \
                 (Ab) + (size_t)r * (Kdim) + ch * 64 + c8 * 8);                       \
        }                                                                             \
        _Pragma("unroll")                                                             \
        for (int i = 0; i < 2; i++) {                                                 \
            int cidx = tid + i * 512;              /* B: 128 rows x 8 x 16B */        \
            int r = cidx >> 3, c8 = cidx & 7;                                         \
            cp16(sb + (uint32_t)(r * GK_STRIDE + c8 * 8) * 2,                         \
                 (Bb) + (size_t)r * (Kdim) + ch * 64 + c8 * 8);                       \
        }                                                                             \
        CP_COMMIT();                                                                  \
    };                                                                                \
    float c[4][4][4];                                                                 \
    _Pragma("unroll")                                                                 \
    for (int i = 0; i < 4; i++)                                                       \
        _Pragma("unroll")                                                             \
        for (int j = 0; j < 4; j++)                                                   \
            _Pragma("unroll")                                                         \
            for (int q = 0; q < 4; q++) c[i][j][q] = 0.f;                             \
    issue(0, 0);                                                                      \
    issue(1, 1);                                                                      \
    for (int ch = 0; ch < nch; ch++) {                                                \
        if (ch + 1 < nch) { CP_WAIT(1); } else { CP_WAIT(0); }                        \
        __syncthreads();                                                              \
        const uint32_t abase = sbase + (uint32_t)((ch % 3) * GSTAGE_HALF) * 2;        \
        const uint32_t bbase = abase + GA_HALF * 2;                                   \
        _Pragma("unroll")                                                             \
        for (int ks = 0; ks < 4; ks++) {                                              \
            const int kk = ks * 16;                                                   \
            uint32_t af[4][4], bf[4][2];                                              \
            _Pragma("unroll")                                                         \
            for (int i = 0; i < 4; i++)                                               \
                ldsm_x4(af[i], abase + (uint32_t)((wm + i * 16 + l_r) * GK_STRIDE + kk + l_c) * 2); \
            _Pragma("unroll")                                                         \
            for (int j2 = 0; j2 < 2; j2++) {                                          \
                uint32_t r4[4];                                                       \
                ldsm_x4(r4, bbase + (uint32_t)((wn + j2 * 16 + l_r) * GK_STRIDE + kk + l_c) * 2);   \
                bf[2 * j2][0] = r4[0];     bf[2 * j2][1] = r4[2];                     \
                bf[2 * j2 + 1][0] = r4[1]; bf[2 * j2 + 1][1] = r4[3];                 \
            }                                                                         \
            _Pragma("unroll")                                                         \
            for (int i = 0; i < 4; i++)                                               \
                _Pragma("unroll")                                                     \
                for (int j = 0; j < 4; j++)                                           \
                    mma_f16(c[i][j], af[i], bf[j]);                                   \
        }                                                                             \
        if (ch + 2 < nch) issue(ch + 2, (ch + 2) % 3);                                \
    }

// ============================================================
// GEMM1 fused: qkv-projection + RoPE + split + scale (fp16 math).
// grid (48, 32). Writes Q/K/V float [B,H,T,hd], tf32-rounded.
// ============================================================
__global__ __launch_bounds__(512, 1) void gemm_qkv_rope(
    const __half* __restrict__ A, const __half* __restrict__ Bt,
    float* __restrict__ Q, float* __restrict__ Kd, float* __restrict__ V)
{
    const uint32_t sbase = smem_u32(dyn_smem);
    const int tid = threadIdx.x;
    const int lane = tid & 31;
    const int w = tid >> 5;
    const int wm = (w & 3) * 64;
    const int wn = (w >> 2) * 32;
    const int grp = lane >> 2;
    const int qid = lane & 3;
    const int l_r = (lane & 7) + ((lane >> 3) & 1) * 8;   // 0..15
    const int l_c = (lane >> 4) * 8;                       // halves: 0 or 8

    const int bm = blockIdx.y, bn = blockIdx.x;
    const __half* Ab = A + (size_t)bm * 256 * DIM_;
    const __half* Bb = Bt + (size_t)bn * 128 * DIM_;

    GEMM_MAINLOOP_F16(Ab, Bb, DIM_)

    const int htype = bn >> 4;           // 0=q, 1=k, 2=v
    const int h = bn & 15;
    float* dst = (htype == 0) ? Q : (htype == 1) ? Kd : V;
    const float scale = (htype == 0) ? 0.08838834764831845f : 1.0f;

#pragma unroll
    for (int i = 0; i < 4; i++) {
        const int grow = bm * 256 + wm + i * 16 + grp;   // b*SEQ + t
        const int b = grow >> 9;
        const int t0 = grow & 511;

        if (htype < 2 && wn == 0) {
#pragma unroll
            for (int q4 = 0; q4 < 4; q4++) {
                const int d = qid * 2 + (q4 & 1);
                const int t = t0 + (q4 >> 1) * 8;
                float inv = expf(-(float)d * (9.210340371976184f / 8.0f));
                float sn, cs;
                sincosf((float)t * inv, &sn, &cs);
                float x1 = c[i][0][q4];
                float x2 = c[i][1][q4];
                c[i][0][q4] = x1 * cs - x2 * sn;
                c[i][1][q4] = x2 * cs + x1 * sn;
            }
        }

        const size_t base0 = ((size_t)((b * NH_ + h) * SEQ_) + t0) * HD_;
#pragma unroll
        for (int j = 0; j < 4; j++) {
            const int col = wn + j * 8 + qid * 2;
            *(float2*)(dst + base0 + col) =
                make_float2(tf32r(c[i][j][0] * scale), tf32r(c[i][j][1] * scale));
            *(float2*)(dst + base0 + 8 * HD_ + col) =
                make_float2(tf32r(c[i][j][2] * scale), tf32r(c[i][j][3] * scale));
        }
    }
}

// ============================================================
// GEMM2: out[M][N] = Yh[M][K] @ Wouth[N][K]^T, fp16 in, fp32 out.
// ============================================================
__global__ __launch_bounds__(512, 1) void gemm_out_f16(
    const __half* __restrict__ A, const __half* __restrict__ Bt,
    float* __restrict__ C, int M, int N, int K)
{
    const uint32_t sbase = smem_u32(dyn_smem);
    const int tid = threadIdx.x;
    const int lane = tid & 31;
    const int w = tid >> 5;
    const int wm = (w & 3) * 64;
    const int wn = (w >> 2) * 32;
    const int grp = lane >> 2;
    const int qid = lane & 3;
    const int l_r = (lane & 7) + ((lane >> 3) & 1) * 8;
    const int l_c = (lane >> 4) * 8;

    const int bm = blockIdx.y, bn = blockIdx.x;
    const __half* Ab = A + (size_t)bm * 256 * K;
    const __half* Bb = Bt + (size_t)bn * 128 * K;

    GEMM_MAINLOOP_F16(Ab, Bb, K)

#pragma unroll
    for (int i = 0; i < 4; i++) {
        const int row = bm * 256 + wm + i * 16 + grp;
#pragma unroll
        for (int j = 0; j < 4; j++) {
            const int col = bn * 128 + wn + j * 8 + qid * 2;
            *(float2*)(C + (size_t)row * N + col)       = make_float2(c[i][j][0], c[i][j][1]);
            *(float2*)(C + (size_t)(row + 8) * N + col) = make_float2(c[i][j][2], c[i][j][3]);
        }
    }
}

// ============================================================
// Tensor-core flash attention (tf32, unchanged math; Y out fp16).
// ============================================================
#define AK_STRIDE 132
#define AV_STRIDE 136
#define AP_STRIDE 76
#define AK_U32 (64 * AK_STRIDE)
#define AV_U32 (64 * AV_STRIDE)
#define AV_OFF (2 * AK_U32)
#define AP_OFF (AV_OFF + 2 * AV_U32)
#define ATT_SMEM_BYTES ((AP_OFF + 8 * 16 * AP_STRIDE) * 4)

__global__ __launch_bounds__(256, 1) void attn_mma_kernel(
    const float* __restrict__ Q, const float* __restrict__ K,
    const float* __restrict__ V, __half* __restrict__ Y)
{
    const uint32_t sbase = smem_u32(dyn_smem);
    uint32_t* smu = (uint32_t*)dyn_smem;

    const int qt = blockIdx.x, bh = blockIdx.y;
    const int tid = threadIdx.x;
    const int lane = tid & 31;
    const int w = tid >> 5;
    const int grp = lane >> 2;
    const int qid = lane & 3;

    const float* Qh = Q + (size_t)bh * SEQ_ * HD_ + (size_t)qt * 128 * HD_;
    const float* Kh = K + (size_t)bh * SEQ_ * HD_;
    const float* Vh = V + (size_t)bh * SEQ_ * HD_;

    const int nch = 2 * qt + 2;

    uint32_t qf[16][4];
    {
#pragma unroll
        for (int i = 0; i < 16; i++) {
            int idx = tid + i * 256;
            int r = idx >> 5, c4 = idx & 31;
            cp16(sbase + (uint32_t)(r * AK_STRIDE + c4 * 4) * 4,
                 Qh + (size_t)r * HD_ + c4 * 4);
        }
        CP_COMMIT();
        CP_WAIT(0);
        __syncthreads();
        const int qrow = w * 16 + grp;
#pragma unroll
        for (int kk = 0; kk < 16; kk++) {
            const uint32_t* qb = smu + qrow * AK_STRIDE + kk * 8;
            qf[kk][0] = qb[qid];
            qf[kk][1] = qb[8 * AK_STRIDE + qid];
            qf[kk][2] = qb[qid + 4];
            qf[kk][3] = qb[8 * AK_STRIDE + qid + 4];
        }
        __syncthreads();
    }

    auto issue_kv = [&](int kc, int s) {
        const uint32_t ks = sbase + (uint32_t)(s * AK_U32) * 4;
        const uint32_t vs = sbase + (uint32_t)(AV_OFF + s * AV_U32) * 4;
#pragma unroll
        for (int i = 0; i < 8; i++) {
            int cidx = tid + i * 256;
            int r = cidx >> 5, c4 = cidx & 31;
            cp16(ks + (uint32_t)(r * AK_STRIDE + c4 * 4) * 4,
                 Kh + (size_t)(kc * 64 + r) * HD_ + c4 * 4);
            cp16(vs + (uint32_t)(r * AV_STRIDE + c4 * 4) * 4,
                 Vh + (size_t)(kc * 64 + r) * HD_ + c4 * 4);
        }
        CP_COMMIT();
    };

    issue_kv(0, 0);
    issue_kv(1, 1);

    uint32_t* Pw = smu + AP_OFF + w * 16 * AP_STRIDE;

    float o[16][4];
#pragma unroll
    for (int j = 0; j < 16; j++)
#pragma unroll
        for (int q = 0; q < 4; q++) o[j][q] = 0.f;
    float m0 = -1e30f, m1 = -1e30f, l0 = 0.f, l1 = 0.f;

    const int r0g = qt * 128 + w * 16 + grp;
    const int r1g = r0g + 8;

    for (int kc = 0; kc < nch; kc++) {
        if (kc + 1 < nch) { CP_WAIT(1); } else { CP_WAIT(0); }
        __syncthreads();

        const uint32_t* Ksb = smu + (kc & 1) * AK_U32;
        const uint32_t* Vsb = smu + AV_OFF + (kc & 1) * AV_U32;

        float s[8][4];
#pragma unroll
        for (int j = 0; j < 8; j++)
#pragma unroll
            for (int q = 0; q < 4; q++) s[j][q] = 0.f;

#pragma unroll
        for (int kk = 0; kk < 16; kk++) {
#pragma unroll
            for (int j = 0; j < 8; j++) {
                uint32_t b[2];
                const uint32_t* kb = Ksb + (j * 8 + grp) * AK_STRIDE + kk * 8;
                b[0] = kb[qid];
                b[1] = kb[qid + 4];
                mma_tf32(s[j], qf[kk], b);
            }
        }

        const int cbase = kc * 64;
#pragma unroll
        for (int j = 0; j < 8; j++) {
            const int c0 = cbase + j * 8 + 2 * qid;
            if (c0 > r0g)     s[j][0] = -1e30f;
            if (c0 + 1 > r0g) s[j][1] = -1e30f;
            if (c0 > r1g)     s[j][2] = -1e30f;
            if (c0 + 1 > r1g) s[j][3] = -1e30f;
        }

        float mc0 = -1e30f, mc1 = -1e30f;
#pragma unroll
        for (int j = 0; j < 8; j++) {
            mc0 = fmaxf(mc0, fmaxf(s[j][0], s[j][1]));
            mc1 = fmaxf(mc1, fmaxf(s[j][2], s[j][3]));
        }
        mc0 = fmaxf(mc0, __shfl_xor_sync(0xFFFFFFFF, mc0, 1));
        mc0 = fmaxf(mc0, __shfl_xor_sync(0xFFFFFFFF, mc0, 2));
        mc1 = fmaxf(mc1, __shfl_xor_sync(0xFFFFFFFF, mc1, 1));
        mc1 = fmaxf(mc1, __shfl_xor_sync(0xFFFFFFFF, mc1, 2));

        const float mn0 = fmaxf(m0, mc0);
        const float mn1 = fmaxf(m1, mc1);
        const float corr0 = __expf(m0 - mn0);
        const float corr1 = __expf(m1 - mn1);
        m0 = mn0; m1 = mn1;

        float ls0 = 0.f, ls1 = 0.f;
#pragma unroll
        for (int j = 0; j < 8; j++) {
            s[j][0] = __expf(s[j][0] - mn0);
            s[j][1] = __expf(s[j][1] - mn0);
            s[j][2] = __expf(s[j][2] - mn1);
            s[j][3] = __expf(s[j][3] - mn1);
            ls0 += s[j][0] + s[j][1];
            ls1 += s[j][2] + s[j][3];
        }
        ls0 += __shfl_xor_sync(0xFFFFFFFF, ls0, 1);
        ls0 += __shfl_xor_sync(0xFFFFFFFF, ls0, 2);
        ls1 += __shfl_xor_sync(0xFFFFFFFF, ls1, 1);
        ls1 += __shfl_xor_sync(0xFFFFFFFF, ls1, 2);
        l0 = l0 * corr0 + ls0;
        l1 = l1 * corr1 + ls1;

#pragma unroll
        for (int j = 0; j < 16; j++) {
            o[j][0] *= corr0; o[j][1] *= corr0;
            o[j][2] *= corr1; o[j][3] *= corr1;
        }

#pragma unroll
        for (int j = 0; j < 8; j++) {
            uint32_t* p0 = Pw + grp * AP_STRIDE + j * 8 + 2 * qid;
            p0[0] = f2tf32(s[j][0]);
            p0[1] = f2tf32(s[j][1]);
            uint32_t* p1 = p0 + 8 * AP_STRIDE;
            p1[0] = f2tf32(s[j][2]);
            p1[1] = f2tf32(s[j][3]);
        }
        __syncwarp();

#pragma unroll
        for (int kk = 0; kk < 8; kk++) {
            uint32_t a[4];
            const uint32_t* pb = Pw + grp * AP_STRIDE + kk * 8;
            a[0] = pb[qid];
            a[1] = pb[8 * AP_STRIDE + qid];
            a[2] = pb[qid + 4];
            a[3] = pb[8 * AP_STRIDE + qid + 4];
#pragma unroll
            for (int j = 0; j < 16; j++) {
                uint32_t b[2];
                const uint32_t* vb = Vsb + (kk * 8 + qid) * AV_STRIDE + j * 8 + grp;
                b[0] = vb[0];
                b[1] = vb[4 * AV_STRIDE];
                mma_tf32(o[j], a, b);
            }
        }

        __syncthreads();
        if (kc + 2 < nch) issue_kv(kc + 2, kc & 1);
    }

    // ---- write Y (B,T,C) as fp16 for GEMM2 ----
    const float inv0 = 1.f / l0;
    const float inv1 = 1.f / l1;
    const int b = bh >> 4, h = bh & 15;
    __half* y0 = Y + ((size_t)(b * SEQ_ + r0g)) * DIM_ + h * HD_;
    __half* y1 = Y + ((size_t)(b * SEQ_ + r1g)) * DIM_ + h * HD_;
#pragma unroll
    for (int j = 0; j < 16; j++) {
        const int col = j * 8 + 2 * qid;
        *(__half2*)(y0 + col) = __floats2half2_rn(o[j][0] * inv0, o[j][1] * inv0);
        *(__half2*)(y1 + col) = __floats2half2_rn(o[j][2] * inv1, o[j][3] * inv1);
    }
}

// ============================================================
// launch
// ============================================================
extern "C" void kernel_launch(void* const* d_in, const int* in_sizes, int n_in,
                              void* d_out, int out_size)
{
    const float* x    = (const float*)d_in[0];
    const float* Wqkv = (const float*)d_in[1];
    const float* Wout = (const float*)d_in[2];
    float* out = (float*)d_out;

    float *Q, *K, *V;
    __half *Yh, *xh, *wqkvh, *wouth;
    cudaGetSymbolAddress((void**)&Q, g_q);
    cudaGetSymbolAddress((void**)&K, g_k);
    cudaGetSymbolAddress((void**)&V, g_v);
    cudaGetSymbolAddress((void**)&Yh, g_yh);
    cudaGetSymbolAddress((void**)&xh, g_xh);
    cudaGetSymbolAddress((void**)&wqkvh, g_wqkvh);
    cudaGetSymbolAddress((void**)&wouth, g_wouth);

    cudaFuncSetAttribute(gemm_qkv_rope, cudaFuncAttributeMaxDynamicSharedMemorySize, GEMM_SMEM_BYTES);
    cudaFuncSetAttribute(gemm_out_f16, cudaFuncAttributeMaxDynamicSharedMemorySize, GEMM_SMEM_BYTES);
    cudaFuncSetAttribute(attn_mma_kernel, cudaFuncAttributeMaxDynamicSharedMemorySize, ATT_SMEM_BYTES);

    // 0) fp16 conversions: x elementwise; weights transpose -> [N][K]
    round_x_h<<<(N4_X + 255) / 256, 256>>>((const float4*)x, (__half2*)xh, N4_X);
    transpose_h_kernel<<<dim3(QKVN_ / 32, DIM_ / 32), dim3(32, 8)>>>(Wqkv, wqkvh, DIM_, QKVN_);
    transpose_h_kernel<<<dim3(DIM_ / 32, DIM_ / 32), dim3(32, 8)>>>(Wout, wouth, DIM_, DIM_);

    // 1) fused qkv-projection + RoPE + split + scale (fp16 tensor cores)
    gemm_qkv_rope<<<dim3(QKVN_ / 128, ROWS_ / 256), 512, GEMM_SMEM_BYTES>>>(xh, wqkvh, Q, K, V);

    // 2) causal attention (tf32) -> Y fp16 (B,T,C)
    attn_mma_kernel<<<dim3(SEQ_ / 128, BATCH_ * NH_), 256, ATT_SMEM_BYTES>>>(Q, K, V, Yh);

    // 3) out = Y @ Wout (fp16 tensor cores, fp32 out)
    gemm_out_f16<<<dim3(DIM_ / 128, ROWS_ / 256), 512, GEMM_SMEM_BYTES>>>(Yh, wouth, out, ROWS_, DIM_, DIM_);
}

// round 16
// speedup vs baseline: 1.7944x; 1.0948x over previous
#include <cuda_runtime.h>
#include <cuda_fp16.h>
#include <math.h>
#include <cstdint>

#define BATCH_ 16
#define SEQ_ 512
#define DIM_ 2048
#define NH_ 16
#define HD_ 128
#define ROWS_ (BATCH_*SEQ_)    // 8192
#define QKVN_ (3*DIM_)         // 6144

// ---- scratch (static device globals; no runtime allocation) ----
__device__ float  g_q[(size_t)BATCH_*NH_*SEQ_*HD_];
__device__ float  g_k[(size_t)BATCH_*NH_*SEQ_*HD_];
__device__ float  g_v[(size_t)BATCH_*NH_*SEQ_*HD_];
__device__ __half g_yh[(size_t)ROWS_ * DIM_];        // attention out, fp16, (B,T,C)
__device__ __half g_xh[(size_t)ROWS_ * DIM_];        // fp16 x
__device__ __half g_wqkvh[(size_t)DIM_ * QKVN_];     // Wqkv^T [6144][2048] fp16
__device__ __half g_wouth[(size_t)DIM_ * DIM_];      // Wout^T [2048][2048] fp16

extern __shared__ char dyn_smem[];

// ============================================================
// helpers
// ============================================================
__device__ __forceinline__ uint32_t f2tf32(float f) {
    uint32_t r;
    asm("cvt.rna.tf32.f32 %0, %1;" : "=r"(r) : "f"(f));
    return r;
}
__device__ __forceinline__ float tf32r(float f) { return __uint_as_float(f2tf32(f)); }

// tf32 mma (attention only)
__device__ __forceinline__ void mma_tf32(float* c, const uint32_t* a, const uint32_t* b) {
    asm volatile(
        "mma.sync.aligned.m16n8k8.row.col.f32.tf32.tf32.f32 "
        "{%0,%1,%2,%3}, {%4,%5,%6,%7}, {%8,%9}, {%0,%1,%2,%3};"
        : "+f"(c[0]), "+f"(c[1]), "+f"(c[2]), "+f"(c[3])
        : "r"(a[0]), "r"(a[1]), "r"(a[2]), "r"(a[3]), "r"(b[0]), "r"(b[1]));
}

// fp16 mma, fp32 accumulate (GEMMs): K=16 per instruction
__device__ __forceinline__ void mma_f16(float* c, const uint32_t* a, const uint32_t* b) {
    asm volatile(
        "mma.sync.aligned.m16n8k16.row.col.f32.f16.f16.f32 "
        "{%0,%1,%2,%3}, {%4,%5,%6,%7}, {%8,%9}, {%0,%1,%2,%3};"
        : "+f"(c[0]), "+f"(c[1]), "+f"(c[2]), "+f"(c[3])
        : "r"(a[0]), "r"(a[1]), "r"(a[2]), "r"(a[3]), "r"(b[0]), "r"(b[1]));
}

__device__ __forceinline__ void ldsm_x4(uint32_t* r, uint32_t addr) {
    asm volatile("ldmatrix.sync.aligned.m8n8.x4.shared.b16 {%0,%1,%2,%3}, [%4];"
        : "=r"(r[0]), "=r"(r[1]), "=r"(r[2]), "=r"(r[3]) : "r"(addr));
}

__device__ __forceinline__ uint32_t smem_u32(const void* p) {
    uint32_t a;
    asm("{ .reg .u64 t; cvta.to.shared.u64 t, %1; cvt.u32.u64 %0, t; }" : "=r"(a) : "l"(p));
    return a;
}
__device__ __forceinline__ void cp16(uint32_t dst, const void* src) {
    asm volatile("cp.async.cg.shared.global [%0], [%1], 16;" :: "r"(dst), "l"(src) : "memory");
}
#define CP_COMMIT() asm volatile("cp.async.commit_group;" ::: "memory")
#define CP_WAIT(n)  asm volatile("cp.async.wait_group %0;" :: "n"(n) : "memory")

// ============================================================
// fp16 conversion kernels
// ============================================================
#define N4_X (ROWS_*DIM_/4)

__global__ __launch_bounds__(256) void round_x_h(
    const float4* __restrict__ in, __half2* __restrict__ out, int n4)
{
    int i = blockIdx.x * blockDim.x + threadIdx.x;
    if (i < n4) {
        float4 v = in[i];
        out[2 * i]     = __floats2half2_rn(v.x, v.y);
        out[2 * i + 1] = __floats2half2_rn(v.z, v.w);
    }
}

// out[c][r] = half(in[r][c]);  in: [R][C] float.  grid (C/32, R/32), block (32,8)
__global__ __launch_bounds__(256) void transpose_h_kernel(
    const float* __restrict__ in, __half* __restrict__ out, int R, int C)
{
    __shared__ float t[32][33];
    const int bx = blockIdx.x * 32, by = blockIdx.y * 32;
    const int tx = threadIdx.x, ty = threadIdx.y;
#pragma unroll
    for (int i = 0; i < 4; i++)
        t[ty + i * 8][tx] = in[(size_t)(by + ty + i * 8) * C + bx + tx];
    __syncthreads();
#pragma unroll
    for (int i = 0; i < 4; i++)
        out[(size_t)(bx + ty + i * 8) * R + by + tx] = __float2half_rn(t[tx][ty + i * 8]);
}

// ============================================================
// fp16 GEMM core: 128x128 block tile, 256 threads (8 warps 2x4),
// warp tile 64x32, BK=64 halves, 3-stage cp.async, ldmatrix b16.
// smem/CTA = 110592 B -> 2 CTAs/SM; regs ~100 -> RF fits 2 CTAs.
// smem row stride 72 halves (144B): ldmatrix conflict-free.
// ============================================================
#define GK_STRIDE 72
#define GT_HALF (128 * GK_STRIDE)          // 9216 halves per tile
#define GSTAGE_HALF (2 * GT_HALF)          // 18432 halves = 36864 B
#define GEMM_SMEM_BYTES (3 * GSTAGE_HALF * 2)   // 110592

#define GEMM_MAINLOOP_F16(Ab, Bb, Kdim)                                               \
    const int nch = (Kdim) / 64;                                                      \
    auto issue = [&](int ch, int s) {                                                 \
        const uint32_t sa = sbase + (uint32_t)(s * GSTAGE_HALF) * 2;                  \
        const uint32_t sb = sa + GT_HALF * 2;                                         \
        _Pragma("unroll")                                                             \
        for (int i = 0; i < 4; i++) {                                                 \
            int cidx = tid + i * 256;              /* 128 rows x 8 x 16B */           \
            int r = cidx >> 3, c8 = cidx & 7;                                         \
            uint32_t off = (uint32_t)(r * GK_STRIDE + c8 * 8) * 2;                    \
            cp16(sa + off, (Ab) + (size_t)r * (Kdim) + ch * 64 + c8 * 8);             \
            cp16(sb + off, (Bb) + (size_t)r * (Kdim) + ch * 64 + c8 * 8);             \
        }                                                                             \
        CP_COMMIT();                                                                  \
    };                                                                                \
    float c[4][4][4];                                                                 \
    _Pragma("unroll")                                                                 \
    for (int i = 0; i < 4; i++)                                                       \
        _Pragma("unroll")                                                             \
        for (int j = 0; j < 4; j++)                                                   \
            _Pragma("unroll")                                                         \
            for (int q = 0; q < 4; q++) c[i][j][q] = 0.f;                             \
    issue(0, 0);                                                                      \
    issue(1, 1);                                                                      \
    for (int ch = 0; ch < nch; ch++) {                                                \
        if (ch + 1 < nch) { CP_WAIT(1); } else { CP_WAIT(0); }                        \
        __syncthreads();                                                              \
        const uint32_t abase = sbase + (uint32_t)((ch % 3) * GSTAGE_HALF) * 2;        \
        const uint32_t bbase = abase + GT_HALF * 2;                                   \
        _Pragma("unroll")                                                             \
        for (int ks = 0; ks < 4; ks++) {                                              \
            const int kk = ks * 16;                                                   \
            uint32_t af[4][4], bf[4][2];                                              \
            _Pragma("unroll")                                                         \
            for (int i = 0; i < 4; i++)                                               \
                ldsm_x4(af[i], abase + (uint32_t)((wm + i * 16 + l_r) * GK_STRIDE + kk + l_c) * 2); \
            _Pragma("unroll")                                                         \
            for (int j2 = 0; j2 < 2; j2++) {                                          \
                uint32_t r4[4];                                                       \
                ldsm_x4(r4, bbase + (uint32_t)((wn + j2 * 16 + l_r) * GK_STRIDE + kk + l_c) * 2);   \
                bf[2 * j2][0] = r4[0];     bf[2 * j2][1] = r4[2];                     \
                bf[2 * j2 + 1][0] = r4[1]; bf[2 * j2 + 1][1] = r4[3];                 \
            }                                                                         \
            _Pragma("unroll")                                                         \
            for (int i = 0; i < 4; i++)                                               \
                _Pragma("unroll")                                                     \
                for (int j = 0; j < 4; j++)                                           \
                    mma_f16(c[i][j], af[i], bf[j]);                                   \
        }                                                                             \
        if (ch + 2 < nch) issue(ch + 2, (ch + 2) % 3);                                \
    }

// ============================================================
// GEMM1 fused: qkv-projection + RoPE + split + scale (fp16 math).
// grid (48, 64). Writes Q/K/V float [B,H,T,hd], tf32-rounded.
// ============================================================
__global__ __launch_bounds__(256, 2) void gemm_qkv_rope(
    const __half* __restrict__ A, const __half* __restrict__ Bt,
    float* __restrict__ Q, float* __restrict__ Kd, float* __restrict__ V)
{
    const uint32_t sbase = smem_u32(dyn_smem);
    const int tid = threadIdx.x;
    const int lane = tid & 31;
    const int w = tid >> 5;
    const int wm = (w & 1) * 64;
    const int wn = (w >> 1) * 32;
    const int grp = lane >> 2;
    const int qid = lane & 3;
    const int l_r = (lane & 7) + ((lane >> 3) & 1) * 8;   // 0..15
    const int l_c = (lane >> 4) * 8;                       // halves: 0 or 8

    const int bm = blockIdx.y, bn = blockIdx.x;
    const __half* Ab = A + (size_t)bm * 128 * DIM_;
    const __half* Bb = Bt + (size_t)bn * 128 * DIM_;

    GEMM_MAINLOOP_F16(Ab, Bb, DIM_)

    const int htype = bn >> 4;           // 0=q, 1=k, 2=v
    const int h = bn & 15;
    float* dst = (htype == 0) ? Q : (htype == 1) ? Kd : V;
    const float scale = (htype == 0) ? 0.08838834764831845f : 1.0f;

#pragma unroll
    for (int i = 0; i < 4; i++) {
        const int grow = bm * 128 + wm + i * 16 + grp;   // b*SEQ + t
        const int b = grow >> 9;
        const int t0 = grow & 511;

        if (htype < 2 && wn == 0) {
#pragma unroll
            for (int q4 = 0; q4 < 4; q4++) {
                const int d = qid * 2 + (q4 & 1);
                const int t = t0 + (q4 >> 1) * 8;
                float inv = expf(-(float)d * (9.210340371976184f / 8.0f));
                float sn, cs;
                sincosf((float)t * inv, &sn, &cs);
                float x1 = c[i][0][q4];
                float x2 = c[i][1][q4];
                c[i][0][q4] = x1 * cs - x2 * sn;
                c[i][1][q4] = x2 * cs + x1 * sn;
            }
        }

        const size_t base0 = ((size_t)((b * NH_ + h) * SEQ_) + t0) * HD_;
#pragma unroll
        for (int j = 0; j < 4; j++) {
            const int col = wn + j * 8 + qid * 2;
            *(float2*)(dst + base0 + col) =
                make_float2(tf32r(c[i][j][0] * scale), tf32r(c[i][j][1] * scale));
            *(float2*)(dst + base0 + 8 * HD_ + col) =
                make_float2(tf32r(c[i][j][2] * scale), tf32r(c[i][j][3] * scale));
        }
    }
}

// ============================================================
// GEMM2: out[M][N] = Yh[M][K] @ Wouth[N][K]^T, fp16 in, fp32 out.
// grid (N/128, M/128)
// ============================================================
__global__ __launch_bounds__(256, 2) void gemm_out_f16(
    const __half* __restrict__ A, const __half* __restrict__ Bt,
    float* __restrict__ C, int M, int N, int K)
{
    const uint32_t sbase = smem_u32(dyn_smem);
    const int tid = threadIdx.x;
    const int lane = tid & 31;
    const int w = tid >> 5;
    const int wm = (w & 1) * 64;
    const int wn = (w >> 1) * 32;
    const int grp = lane >> 2;
    const int qid = lane & 3;
    const int l_r = (lane & 7) + ((lane >> 3) & 1) * 8;
    const int l_c = (lane >> 4) * 8;

    const int bm = blockIdx.y, bn = blockIdx.x;
    const __half* Ab = A + (size_t)bm * 128 * K;
    const __half* Bb = Bt + (size_t)bn * 128 * K;

    GEMM_MAINLOOP_F16(Ab, Bb, K)

#pragma unroll
    for (int i = 0; i < 4; i++) {
        const int row = bm * 128 + wm + i * 16 + grp;
#pragma unroll
        for (int j = 0; j < 4; j++) {
            const int col = bn * 128 + wn + j * 8 + qid * 2;
            *(float2*)(C + (size_t)row * N + col)       = make_float2(c[i][j][0], c[i][j][1]);
            *(float2*)(C + (size_t)(row + 8) * N + col) = make_float2(c[i][j][2], c[i][j][3]);
        }
    }
}

// ============================================================
// Tensor-core flash attention (tf32, unchanged math; Y out fp16).
// ============================================================
#define AK_STRIDE 132
#define AV_STRIDE 136
#define AP_STRIDE 76
#define AK_U32 (64 * AK_STRIDE)
#define AV_U32 (64 * AV_STRIDE)
#define AV_OFF (2 * AK_U32)
#define AP_OFF (AV_OFF + 2 * AV_U32)
#define ATT_SMEM_BYTES ((AP_OFF + 8 * 16 * AP_STRIDE) * 4)

__global__ __launch_bounds__(256, 1) void attn_mma_kernel(
    const float* __restrict__ Q, const float* __restrict__ K,
    const float* __restrict__ V, __half* __restrict__ Y)
{
    const uint32_t sbase = smem_u32(dyn_smem);
    uint32_t* smu = (uint32_t*)dyn_smem;

    const int qt = blockIdx.x, bh = blockIdx.y;
    const int tid = threadIdx.x;
    const int lane = tid & 31;
    const int w = tid >> 5;
    const int grp = lane >> 2;
    const int qid = lane & 3;

    const float* Qh = Q + (size_t)bh * SEQ_ * HD_ + (size_t)qt * 128 * HD_;
    const float* Kh = K + (size_t)bh * SEQ_ * HD_;
    const float* Vh = V + (size_t)bh * SEQ_ * HD_;

    const int nch = 2 * qt + 2;

    uint32_t qf[16][4];
    {
#pragma unroll
        for (int i = 0; i < 16; i++) {
            int idx = tid + i * 256;
            int r = idx >> 5, c4 = idx & 31;
            cp16(sbase + (uint32_t)(r * AK_STRIDE + c4 * 4) * 4,
                 Qh + (size_t)r * HD_ + c4 * 4);
        }
        CP_COMMIT();
        CP_WAIT(0);
        __syncthreads();
        const int qrow = w * 16 + grp;
#pragma unroll
        for (int kk = 0; kk < 16; kk++) {
            const uint32_t* qb = smu + qrow * AK_STRIDE + kk * 8;
            qf[kk][0] = qb[qid];
            qf[kk][1] = qb[8 * AK_STRIDE + qid];
            qf[kk][2] = qb[qid + 4];
            qf[kk][3] = qb[8 * AK_STRIDE + qid + 4];
        }
        __syncthreads();
    }

    auto issue_kv = [&](int kc, int s) {
        const uint32_t ks = sbase + (uint32_t)(s * AK_U32) * 4;
        const uint32_t vs = sbase + (uint32_t)(AV_OFF + s * AV_U32) * 4;
#pragma unroll
        for (int i = 0; i < 8; i++) {
            int cidx = tid + i * 256;
            int r = cidx >> 5, c4 = cidx & 31;
            cp16(ks + (uint32_t)(r * AK_STRIDE + c4 * 4) * 4,
                 Kh + (size_t)(kc * 64 + r) * HD_ + c4 * 4);
            cp16(vs + (uint32_t)(r * AV_STRIDE + c4 * 4) * 4,
                 Vh + (size_t)(kc * 64 + r) * HD_ + c4 * 4);
        }
        CP_COMMIT();
    };

    issue_kv(0, 0);
    issue_kv(1, 1);

    uint32_t* Pw = smu + AP_OFF + w * 16 * AP_STRIDE;

    float o[16][4];
#pragma unroll
    for (int j = 0; j < 16; j++)
#pragma unroll
        for (int q = 0; q < 4; q++) o[j][q] = 0.f;
    float m0 = -1e30f, m1 = -1e30f, l0 = 0.f, l1 = 0.f;

    const int r0g = qt * 128 + w * 16 + grp;
    const int r1g = r0g + 8;

    for (int kc = 0; kc < nch; kc++) {
        if (kc + 1 < nch) { CP_WAIT(1); } else { CP_WAIT(0); }
        __syncthreads();

        const uint32_t* Ksb = smu + (kc & 1) * AK_U32;
        const uint32_t* Vsb = smu + AV_OFF + (kc & 1) * AV_U32;

        float s[8][4];
#pragma unroll
        for (int j = 0; j < 8; j++)
#pragma unroll
            for (int q = 0; q < 4; q++) s[j][q] = 0.f;

#pragma unroll
        for (int kk = 0; kk < 16; kk++) {
#pragma unroll
            for (int j = 0; j < 8; j++) {
                uint32_t b[2];
                const uint32_t* kb = Ksb + (j * 8 + grp) * AK_STRIDE + kk * 8;
                b[0] = kb[qid];
                b[1] = kb[qid + 4];
                mma_tf32(s[j], qf[kk], b);
            }
        }

        const int cbase = kc * 64;
#pragma unroll
        for (int j = 0; j < 8; j++) {
            const int c0 = cbase + j * 8 + 2 * qid;
            if (c0 > r0g)     s[j][0] = -1e30f;
            if (c0 + 1 > r0g) s[j][1] = -1e30f;
            if (c0 > r1g)     s[j][2] = -1e30f;
            if (c0 + 1 > r1g) s[j][3] = -1e30f;
        }

        float mc0 = -1e30f, mc1 = -1e30f;
#pragma unroll
        for (int j = 0; j < 8; j++) {
            mc0 = fmaxf(mc0, fmaxf(s[j][0], s[j][1]));
            mc1 = fmaxf(mc1, fmaxf(s[j][2], s[j][3]));
        }
        mc0 = fmaxf(mc0, __shfl_xor_sync(0xFFFFFFFF, mc0, 1));
        mc0 = fmaxf(mc0, __shfl_xor_sync(0xFFFFFFFF, mc0, 2));
        mc1 = fmaxf(mc1, __shfl_xor_sync(0xFFFFFFFF, mc1, 1));
        mc1 = fmaxf(mc1, __shfl_xor_sync(0xFFFFFFFF, mc1, 2));

        const float mn0 = fmaxf(m0, mc0);
        const float mn1 = fmaxf(m1, mc1);
        const float corr0 = __expf(m0 - mn0);
        const float corr1 = __expf(m1 - mn1);
        m0 = mn0; m1 = mn1;

        float ls0 = 0.f, ls1 = 0.f;
#pragma unroll
        for (int j = 0; j < 8; j++) {
            s[j][0] = __expf(s[j][0] - mn0);
            s[j][1] = __expf(s[j][1] - mn0);
            s[j][2] = __expf(s[j][2] - mn1);
            s[j][3] = __expf(s[j][3] - mn1);
            ls0 += s[j][0] + s[j][1];
            ls1 += s[j][2] + s[j][3];
        }
        ls0 += __shfl_xor_sync(0xFFFFFFFF, ls0, 1);
        ls0 += __shfl_xor_sync(0xFFFFFFFF, ls0, 2);
        ls1 += __shfl_xor_sync(0xFFFFFFFF, ls1, 1);
        ls1 += __shfl_xor_sync(0xFFFFFFFF, ls1, 2);
        l0 = l0 * corr0 + ls0;
        l1 = l1 * corr1 + ls1;

#pragma unroll
        for (int j = 0; j < 16; j++) {
            o[j][0] *= corr0; o[j][1] *= corr0;
            o[j][2] *= corr1; o[j][3] *= corr1;
        }

#pragma unroll
        for (int j = 0; j < 8; j++) {
            uint32_t* p0 = Pw + grp * AP_STRIDE + j * 8 + 2 * qid;
            p0[0] = f2tf32(s[j][0]);
            p0[1] = f2tf32(s[j][1]);
            uint32_t* p1 = p0 + 8 * AP_STRIDE;
            p1[0] = f2tf32(s[j][2]);
            p1[1] = f2tf32(s[j][3]);
        }
        __syncwarp();

#pragma unroll
        for (int kk = 0; kk < 8; kk++) {
            uint32_t a[4];
            const uint32_t* pb = Pw + grp * AP_STRIDE + kk * 8;
            a[0] = pb[qid];
            a[1] = pb[8 * AP_STRIDE + qid];
            a[2] = pb[qid + 4];
            a[3] = pb[8 * AP_STRIDE + qid + 4];
#pragma unroll
            for (int j = 0; j < 16; j++) {
                uint32_t b[2];
                const uint32_t* vb = Vsb + (kk * 8 + qid) * AV_STRIDE + j * 8 + grp;
                b[0] = vb[0];
                b[1] = vb[4 * AV_STRIDE];
                mma_tf32(o[j], a, b);
            }
        }

        __syncthreads();
        if (kc + 2 < nch) issue_kv(kc + 2, kc & 1);
    }

    // ---- write Y (B,T,C) as fp16 for GEMM2 ----
    const float inv0 = 1.f / l0;
    const float inv1 = 1.f / l1;
    const int b = bh >> 4, h = bh & 15;
    __half* y0 = Y + ((size_t)(b * SEQ_ + r0g)) * DIM_ + h * HD_;
    __half* y1 = Y + ((size_t)(b * SEQ_ + r1g)) * DIM_ + h * HD_;
#pragma unroll
    for (int j = 0; j < 16; j++) {
        const int col = j * 8 + 2 * qid;
        *(__half2*)(y0 + col) = __floats2half2_rn(o[j][0] * inv0, o[j][1] * inv0);
        *(__half2*)(y1 + col) = __floats2half2_rn(o[j][2] * inv1, o[j][3] * inv1);
    }
}

// ============================================================
// launch
// ============================================================
extern "C" void kernel_launch(void* const* d_in, const int* in_sizes, int n_in,
                              void* d_out, int out_size)
{
    const float* x    = (const float*)d_in[0];
    const float* Wqkv = (const float*)d_in[1];
    const float* Wout = (const float*)d_in[2];
    float* out = (float*)d_out;

    float *Q, *K, *V;
    __half *Yh, *xh, *wqkvh, *wouth;
    cudaGetSymbolAddress((void**)&Q, g_q);
    cudaGetSymbolAddress((void**)&K, g_k);
    cudaGetSymbolAddress((void**)&V, g_v);
    cudaGetSymbolAddress((void**)&Yh, g_yh);
    cudaGetSymbolAddress((void**)&xh, g_xh);
    cudaGetSymbolAddress((void**)&wqkvh, g_wqkvh);
    cudaGetSymbolAddress((void**)&wouth, g_wouth);

    cudaFuncSetAttribute(gemm_qkv_rope, cudaFuncAttributeMaxDynamicSharedMemorySize, GEMM_SMEM_BYTES);
    cudaFuncSetAttribute(gemm_out_f16, cudaFuncAttributeMaxDynamicSharedMemorySize, GEMM_SMEM_BYTES);
    cudaFuncSetAttribute(attn_mma_kernel, cudaFuncAttributeMaxDynamicSharedMemorySize, ATT_SMEM_BYTES);

    // 0) fp16 conversions: x elementwise; weights transpose -> [N][K]
    round_x_h<<<(N4_X + 255) / 256, 256>>>((const float4*)x, (__half2*)xh, N4_X);
    transpose_h_kernel<<<dim3(QKVN_ / 32, DIM_ / 32), dim3(32, 8)>>>(Wqkv, wqkvh, DIM_, QKVN_);
    transpose_h_kernel<<<dim3(DIM_ / 32, DIM_ / 32), dim3(32, 8)>>>(Wout, wouth, DIM_, DIM_);

    // 1) fused qkv-projection + RoPE + split + scale (fp16 tensor cores, 2 CTA/SM)
    gemm_qkv_rope<<<dim3(QKVN_ / 128, ROWS_ / 128), 256, GEMM_SMEM_BYTES>>>(xh, wqkvh, Q, K, V);

    // 2) causal attention (tf32) -> Y fp16 (B,T,C)
    attn_mma_kernel<<<dim3(SEQ_ / 128, BATCH_ * NH_), 256, ATT_SMEM_BYTES>>>(Q, K, V, Yh);

    // 3) out = Y @ Wout (fp16 tensor cores, fp32 out, 2 CTA/SM)
    gemm_out_f16<<<dim3(DIM_ / 128, ROWS_ / 128), 256, GEMM_SMEM_BYTES>>>(Yh, wouth, out, ROWS_, DIM_, DIM_);
}